// round 1
// baseline (speedup 1.0000x reference)
#include <cuda_runtime.h>
#include <cuda_bf16.h>

// ---------------------------------------------------------------------------
// EncoderLayer: B=16, N1=4, N2=4, N=256, E=256, H=8, DK=32
// T = B*N1*N2*N = 65536 tokens, E = 256, FF = 1024
// ---------------------------------------------------------------------------

#define T_TOK  65536
#define E_DIM  256
#define FF_DIM 1024
#define N_SEQ  256
#define NHEAD  8
#define DK     32
#define SCALING 0.17677669529663687f   // 32^-0.5
#define LN_EPS 1e-5f

// Scratch (device globals: no allocation allowed in kernel_launch)
__device__ float g_q   [T_TOK * E_DIM];
__device__ float g_k   [T_TOK * E_DIM];
__device__ float g_v   [T_TOK * E_DIM];
__device__ float g_attn[T_TOK * E_DIM];
__device__ float g_y1  [T_TOK * E_DIM];
__device__ float g_h1  [T_TOK * E_DIM];
__device__ float g_hid [T_TOK * FF_DIM];
__device__ float g_y2  [T_TOK * E_DIM];

// ---------------------------------------------------------------------------
// SGEMM: C[M,N] = act( alpha * A[M,K] @ B[K,N] + bias + resid )
// 128x128 tile, BK=8, 256 threads, 8x8 per thread.
// Requires M%128==0, N%128==0, K%8==0 (true for all calls here).
// ---------------------------------------------------------------------------
template<bool BIAS, bool RELU, bool RES>
__global__ __launch_bounds__(256) void sgemm128(
    const float* __restrict__ A, const float* __restrict__ B,
    float* __restrict__ C, int N, int K, float alpha,
    const float* __restrict__ bias, const float* __restrict__ resid)
{
    __shared__ float As[8][128];
    __shared__ float Bs[8][128];

    const int tid = threadIdx.x;
    const int m0 = blockIdx.y * 128;
    const int n0 = blockIdx.x * 128;

    // A tile load mapping: thread -> (row, 4 k-cols)
    const int arow = tid >> 1;
    const int acol = (tid & 1) * 4;
    // B tile load mapping: thread -> (k-row, 4 n-cols)
    const int brow = tid >> 5;
    const int bcol = (tid & 31) * 4;

    const float* Aptr = A + (long)(m0 + arow) * K + acol;
    const float* Bptr = B + (long)brow * N + n0 + bcol;

    const int ty = tid >> 4;
    const int tx = tid & 15;

    float acc[8][8];
#pragma unroll
    for (int i = 0; i < 8; i++)
#pragma unroll
        for (int j = 0; j < 8; j++) acc[i][j] = 0.f;

    for (int k0 = 0; k0 < K; k0 += 8) {
        float4 av = *(const float4*)(Aptr + k0);
        float4 bv = *(const float4*)(Bptr + (long)k0 * N);
        As[acol + 0][arow] = av.x;
        As[acol + 1][arow] = av.y;
        As[acol + 2][arow] = av.z;
        As[acol + 3][arow] = av.w;
        *(float4*)&Bs[brow][bcol] = bv;
        __syncthreads();
#pragma unroll
        for (int k = 0; k < 8; k++) {
            float a[8], b[8];
            *(float4*)(a)     = *(const float4*)&As[k][ty * 8];
            *(float4*)(a + 4) = *(const float4*)&As[k][ty * 8 + 4];
            *(float4*)(b)     = *(const float4*)&Bs[k][tx * 8];
            *(float4*)(b + 4) = *(const float4*)&Bs[k][tx * 8 + 4];
#pragma unroll
            for (int i = 0; i < 8; i++)
#pragma unroll
                for (int j = 0; j < 8; j++)
                    acc[i][j] = fmaf(a[i], b[j], acc[i][j]);
        }
        __syncthreads();
    }

    // Epilogue
#pragma unroll
    for (int i = 0; i < 8; i++) {
        const int row = m0 + ty * 8 + i;
#pragma unroll
        for (int j = 0; j < 8; j += 4) {
            const int col = n0 + tx * 8 + j;
            float4 r;
            r.x = acc[i][j + 0] * alpha;
            r.y = acc[i][j + 1] * alpha;
            r.z = acc[i][j + 2] * alpha;
            r.w = acc[i][j + 3] * alpha;
            if (BIAS) {
                const float4 bb = *(const float4*)(bias + col);
                r.x += bb.x; r.y += bb.y; r.z += bb.z; r.w += bb.w;
            }
            if (RES) {
                const float4 rr = *(const float4*)(resid + (long)row * N + col);
                r.x += rr.x; r.y += rr.y; r.z += rr.z; r.w += rr.w;
            }
            if (RELU) {
                r.x = fmaxf(r.x, 0.f); r.y = fmaxf(r.y, 0.f);
                r.z = fmaxf(r.z, 0.f); r.w = fmaxf(r.w, 0.f);
            }
            *(float4*)(C + (long)row * N + col) = r;
        }
    }
}

// ---------------------------------------------------------------------------
// Attention: one CTA per (group g, head h); g = b*16 + n1*4 + n2, 2048 CTAs.
// q pre-scaled. Online softmax, K/V staged in SMEM in two 128-row chunks.
// ---------------------------------------------------------------------------
__global__ __launch_bounds__(256) void attn_kernel(
    const float* __restrict__ q, const float* __restrict__ k,
    const float* __restrict__ v, const float* __restrict__ mask,
    float* __restrict__ out)
{
    __shared__ float ks[128][36];   // padded: float4-aligned, conflict-free
    __shared__ float vs[128][36];

    const int bx = blockIdx.x;
    const int g  = bx >> 3;
    const int h  = bx & 7;
    const long base = (long)g * N_SEQ;      // token row base
    const int hoff = h * DK;
    const int n12 = g & 15;                 // n1*4 + n2
    const int tid = threadIdx.x;            // query row i

    // Load my query row into registers
    float qr[DK];
    {
        const float* qp = q + (base + tid) * E_DIM + hoff;
#pragma unroll
        for (int d = 0; d < DK; d += 4)
            *(float4*)&qr[d] = *(const float4*)(qp + d);
    }

    const float* mrow = mask + ((long)n12 * N_SEQ + tid) * N_SEQ;

    float m = -1e30f, l = 0.f;
    float acc[DK];
#pragma unroll
    for (int d = 0; d < DK; d++) acc[d] = 0.f;

    for (int c = 0; c < 2; c++) {
        __syncthreads();   // previous chunk fully consumed
        {
            const int r = tid & 127;
            const float* src = ((tid < 128) ? k : v) + (base + c * 128 + r) * E_DIM + hoff;
            float (*dst)[36] = (tid < 128) ? ks : vs;
#pragma unroll
            for (int d = 0; d < DK; d += 4)
                *(float4*)&dst[r][d] = *(const float4*)(src + d);
        }
        __syncthreads();

        const float* mp = mrow + c * 128;
        for (int j = 0; j < 128; j++) {
            float s0 = 0.f, s1 = 0.f;
#pragma unroll
            for (int d = 0; d < DK; d += 2) {
                s0 = fmaf(qr[d],     ks[j][d],     s0);
                s1 = fmaf(qr[d + 1], ks[j][d + 1], s1);
            }
            float s = s0 + s1 + mp[j];
            if (s > m) {
                const float cfac = __expf(m - s);
                l *= cfac;
#pragma unroll
                for (int d = 0; d < DK; d++) acc[d] *= cfac;
                m = s;
            }
            const float p = __expf(s - m);
            l += p;
#pragma unroll
            for (int d = 0; d < DK; d++)
                acc[d] = fmaf(p, vs[j][d], acc[d]);
        }
    }

    const float inv = 1.f / l;
    float* op = out + (base + tid) * E_DIM + hoff;
#pragma unroll
    for (int d = 0; d < DK; d += 4) {
        float4 r;
        r.x = acc[d + 0] * inv; r.y = acc[d + 1] * inv;
        r.z = acc[d + 2] * inv; r.w = acc[d + 3] * inv;
        *(float4*)(op + d) = r;
    }
}

// ---------------------------------------------------------------------------
// LayerNorm over E=256 (population variance), one CTA per token row.
// ---------------------------------------------------------------------------
__global__ __launch_bounds__(256) void layernorm_kernel(
    const float* __restrict__ in, const float* __restrict__ g,
    const float* __restrict__ b, float* __restrict__ out)
{
    const long row = blockIdx.x;
    const int tid = threadIdx.x;
    const float vv = in[row * E_DIM + tid];

    float s = vv, sq = vv * vv;
#pragma unroll
    for (int o = 16; o; o >>= 1) {
        s  += __shfl_xor_sync(0xffffffffu, s,  o);
        sq += __shfl_xor_sync(0xffffffffu, sq, o);
    }
    __shared__ float ss[8], ssq[8];
    if ((tid & 31) == 0) { ss[tid >> 5] = s; ssq[tid >> 5] = sq; }
    __syncthreads();
    float S = 0.f, SQ = 0.f;
#pragma unroll
    for (int i = 0; i < 8; i++) { S += ss[i]; SQ += ssq[i]; }

    const float mean = S * (1.f / E_DIM);
    const float var  = SQ * (1.f / E_DIM) - mean * mean;
    const float r    = rsqrtf(var + LN_EPS);
    out[row * E_DIM + tid] = (vv - mean) * r * g[tid] + b[tid];
}

// ---------------------------------------------------------------------------
extern "C" void kernel_launch(void* const* d_in, const int* in_sizes, int n_in,
                              void* d_out, int out_size)
{
    const float* x     = (const float*)d_in[0];
    const float* mask  = (const float*)d_in[1];
    const float* Wq    = (const float*)d_in[2];
    const float* Wk    = (const float*)d_in[3];
    const float* Wv    = (const float*)d_in[4];
    const float* Wo    = (const float*)d_in[5];
    const float* bo    = (const float*)d_in[6];
    const float* W1    = (const float*)d_in[7];
    const float* bf1   = (const float*)d_in[8];
    const float* W2    = (const float*)d_in[9];
    const float* bf2   = (const float*)d_in[10];
    const float* g1    = (const float*)d_in[11];
    const float* beta1 = (const float*)d_in[12];
    const float* g2    = (const float*)d_in[13];
    const float* beta2 = (const float*)d_in[14];
    float* out = (float*)d_out;

    float *q, *k, *v, *attn, *y1, *h1, *hid, *y2;
    cudaGetSymbolAddress((void**)&q,    g_q);
    cudaGetSymbolAddress((void**)&k,    g_k);
    cudaGetSymbolAddress((void**)&v,    g_v);
    cudaGetSymbolAddress((void**)&attn, g_attn);
    cudaGetSymbolAddress((void**)&y1,   g_y1);
    cudaGetSymbolAddress((void**)&h1,   g_h1);
    cudaGetSymbolAddress((void**)&hid,  g_hid);
    cudaGetSymbolAddress((void**)&y2,   g_y2);

    const dim3 blk(256);
    const dim3 gE(E_DIM / 128, T_TOK / 128);    // (2, 512)
    const dim3 gF(FF_DIM / 128, T_TOK / 128);   // (8, 512)

    // QKV projections
    sgemm128<false, false, false><<<gE, blk>>>(x, Wq, q, E_DIM, E_DIM, SCALING, nullptr, nullptr);
    sgemm128<false, false, false><<<gE, blk>>>(x, Wk, k, E_DIM, E_DIM, 1.f, nullptr, nullptr);
    sgemm128<false, false, false><<<gE, blk>>>(x, Wv, v, E_DIM, E_DIM, 1.f, nullptr, nullptr);

    // Attention
    attn_kernel<<<2048, blk>>>(q, k, v, mask, attn);

    // y1 = x + attn @ Wo + bo ; h1 = LN1(y1)
    sgemm128<true, false, true><<<gE, blk>>>(attn, Wo, y1, E_DIM, E_DIM, 1.f, bo, x);
    layernorm_kernel<<<T_TOK, blk>>>(y1, g1, beta1, h1);

    // hid = relu(h1 @ W1 + bf1)
    sgemm128<true, true, false><<<gF, blk>>>(h1, W1, hid, FF_DIM, E_DIM, 1.f, bf1, nullptr);

    // y2 = h1 + hid @ W2 + bf2 ; out = LN2(y2)
    sgemm128<true, false, true><<<gE, blk>>>(hid, W2, y2, E_DIM, FF_DIM, 1.f, bf2, h1);
    layernorm_kernel<<<T_TOK, blk>>>(y2, g2, beta2, out);
}

// round 3
// speedup vs baseline: 1.9520x; 1.9520x over previous
#include <cuda_runtime.h>
#include <cstdint>

// ---------------------------------------------------------------------------
// EncoderLayer: B=16, N1=4, N2=4, N=256, E=256, H=8, DK=32
// T = 65536 tokens, E = 256, FF = 1024
// GEMMs: mma.sync tf32 (m16n8k8) + cp.async + ldmatrix. Attention/LN fp32.
// ---------------------------------------------------------------------------

#define T_TOK  65536
#define E_DIM  256
#define FF_DIM 1024
#define N_SEQ  256
#define DK     32
#define SCALING 0.17677669529663687f
#define LN_EPS 1e-5f

// ---------------- scratch (device globals; no allocs allowed) --------------
__device__ float g_xr  [T_TOK * E_DIM];
__device__ float g_q   [T_TOK * E_DIM];
__device__ float g_k   [T_TOK * E_DIM];
__device__ float g_v   [T_TOK * E_DIM];
__device__ float g_attn[T_TOK * E_DIM];
__device__ float g_y1  [T_TOK * E_DIM];
__device__ float g_h1  [T_TOK * E_DIM];
__device__ float g_h1r [T_TOK * E_DIM];
__device__ float g_hid [T_TOK * FF_DIM];
__device__ float g_y2  [T_TOK * E_DIM];
__device__ float g_WqT [E_DIM * E_DIM];
__device__ float g_WkT [E_DIM * E_DIM];
__device__ float g_WvT [E_DIM * E_DIM];
__device__ float g_WoT [E_DIM * E_DIM];
__device__ float g_W1T [FF_DIM * E_DIM];
__device__ float g_W2T [E_DIM * FF_DIM];

// ---------------- helpers ---------------------------------------------------
__device__ __forceinline__ uint32_t s2u(const void* p) {
    uint32_t a;
    asm("{ .reg .u64 t; cvta.to.shared.u64 t, %1; cvt.u32.u64 %0, t; }" : "=r"(a) : "l"(p));
    return a;
}
__device__ __forceinline__ float rna_tf32(float x) {
    uint32_t u;
    asm("cvt.rna.tf32.f32 %0, %1;" : "=r"(u) : "f"(x));
    return __uint_as_float(u);
}
#define SWZ(o) ((o) ^ (((o) >> 3) & 0x70))

__device__ __forceinline__ void cpa16(uint32_t s, const void* g) {
    asm volatile("cp.async.cg.shared.global [%0], [%1], 16;" :: "r"(s), "l"(g));
}
#define CP_COMMIT() asm volatile("cp.async.commit_group;" ::: "memory")

__device__ __forceinline__ void ldsm4(uint32_t addr, uint32_t* r) {
    asm volatile("ldmatrix.sync.aligned.m8n8.x4.shared.b16 {%0,%1,%2,%3}, [%4];"
                 : "=r"(r[0]), "=r"(r[1]), "=r"(r[2]), "=r"(r[3]) : "r"(addr));
}
__device__ __forceinline__ void mma8(float* c, const uint32_t* a, const uint32_t* b) {
    asm volatile("mma.sync.aligned.m16n8k8.row.col.f32.tf32.tf32.f32 "
                 "{%0,%1,%2,%3}, {%4,%5,%6,%7}, {%8,%9}, {%0,%1,%2,%3};"
                 : "+f"(c[0]), "+f"(c[1]), "+f"(c[2]), "+f"(c[3])
                 : "r"(a[0]), "r"(a[1]), "r"(a[2]), "r"(a[3]), "r"(b[0]), "r"(b[1]));
}

// ---------------------------------------------------------------------------
// GEMM: C[M,Nt] = act(alpha * A[M,Kt] @ BT[Nt,Kt]^T + bias + resid)
// CTA 128x128, BK=32, 3-stage cp.async, 8 warps (4m x 2n), warp 32x64.
// ---------------------------------------------------------------------------
#define BM 128
#define BN 128
#define BK 32
#define STG 3
#define ASZ (BM * BK * 4)        // 16384
#define BSZ (BN * BK * 4)        // 16384
#define STGB (ASZ + BSZ)         // 32768
#define GSMEM (STG * STGB)       // 98304

template<bool BIAS, bool RELU, bool RES, bool ROUND>
__global__ __launch_bounds__(256, 1) void gemm_mma(
    const float* __restrict__ A, const float* __restrict__ BT,
    float* __restrict__ C, int Nt, int Kt, float alpha,
    const float* __restrict__ bias, const float* __restrict__ resid)
{
    extern __shared__ char smem[];
    const uint32_t sb = s2u(smem);
    const int tid = threadIdx.x;
    const int lane = tid & 31;
    const int wid = tid >> 5;
    const int wm = wid & 3;          // 0..3 (M)
    const int wn = wid >> 2;         // 0..1 (N)

    const int m0 = blockIdx.y * BM;
    const int n0 = blockIdx.x * BN;
    const float* Ag = A + (size_t)m0 * Kt;
    const float* Bg = BT + (size_t)n0 * Kt;
    const int nC = Kt / BK;

    // per-thread staging mapping (4 chunks each for A and B)
    const int r_a = tid >> 1;                // not used; mapping below
    (void)r_a;

    auto load_stage = [&](int s, int c) {
        const uint32_t ab = sb + s * STGB;
        const uint32_t bb = ab + ASZ;
        const float* Ac = Ag + c * BK;
        const float* Bc = Bg + c * BK;
#pragma unroll
        for (int i = 0; i < 4; i++) {
            int g = i * 256 + tid, r = g >> 3, cc = g & 7;
            cpa16(ab + SWZ(r * 128 + cc * 16), Ac + (size_t)r * Kt + cc * 4);
        }
#pragma unroll
        for (int i = 0; i < 4; i++) {
            int g = i * 256 + tid, r = g >> 3, cc = g & 7;
            cpa16(bb + SWZ(r * 128 + cc * 16), Bc + (size_t)r * Kt + cc * 4);
        }
    };

    load_stage(0, 0);
    CP_COMMIT();
    load_stage(1, 1);
    CP_COMMIT();

    float acc[2][8][4];
#pragma unroll
    for (int tm = 0; tm < 2; tm++)
#pragma unroll
        for (int j = 0; j < 8; j++)
#pragma unroll
            for (int e = 0; e < 4; e++) acc[tm][j][e] = 0.f;

    // ldmatrix per-thread address components
    const int a_row = wm * 32 + (lane & 15);
    const int a_cb  = (lane >> 4) * 16;
    const int b_row = wn * 64 + (lane & 7) + ((lane >> 4) << 3);
    const int b_cb  = ((lane >> 3) & 1) * 16;

    for (int c = 0; c < nC; c++) {
        const int s = c % STG;
        asm volatile("cp.async.wait_group 1;" ::: "memory");
        __syncthreads();
        const uint32_t ab = sb + s * STGB;
        const uint32_t bb = ab + ASZ;
#pragma unroll
        for (int k8 = 0; k8 < 4; k8++) {
            uint32_t afr[2][4], bfr[8][2];
#pragma unroll
            for (int tm = 0; tm < 2; tm++)
                ldsm4(ab + SWZ((a_row + tm * 16) * 128 + k8 * 32 + a_cb), afr[tm]);
#pragma unroll
            for (int p = 0; p < 4; p++) {
                uint32_t r[4];
                ldsm4(bb + SWZ((b_row + p * 16) * 128 + k8 * 32 + b_cb), r);
                bfr[2 * p][0] = r[0]; bfr[2 * p][1] = r[1];
                bfr[2 * p + 1][0] = r[2]; bfr[2 * p + 1][1] = r[3];
            }
#pragma unroll
            for (int tm = 0; tm < 2; tm++)
#pragma unroll
                for (int j = 0; j < 8; j++)
                    mma8(acc[tm][j], afr[tm], bfr[j]);
        }
        __syncthreads();
        const int cn = c + STG - 1;
        if (cn < nC) load_stage(cn % STG, cn);
        CP_COMMIT();
    }

    // epilogue
    const int mrow = m0 + wm * 32 + (lane >> 2);
    const int ncol = n0 + wn * 64 + (lane & 3) * 2;
#pragma unroll
    for (int tm = 0; tm < 2; tm++) {
#pragma unroll
        for (int j = 0; j < 8; j++) {
            const int gc = ncol + j * 8;
#pragma unroll
            for (int h = 0; h < 2; h++) {
                const int gr = mrow + tm * 16 + h * 8;
                float v0 = acc[tm][j][2 * h + 0] * alpha;
                float v1 = acc[tm][j][2 * h + 1] * alpha;
                if (BIAS) {
                    const float2 bb = *(const float2*)(bias + gc);
                    v0 += bb.x; v1 += bb.y;
                }
                if (RES) {
                    const float2 rr = *(const float2*)(resid + (size_t)gr * Nt + gc);
                    v0 += rr.x; v1 += rr.y;
                }
                if (RELU) { v0 = fmaxf(v0, 0.f); v1 = fmaxf(v1, 0.f); }
                if (ROUND) { v0 = rna_tf32(v0); v1 = rna_tf32(v1); }
                *(float2*)(C + (size_t)gr * Nt + gc) = make_float2(v0, v1);
            }
        }
    }
}

// ---------------------------------------------------------------------------
// Prep kernels
// ---------------------------------------------------------------------------
__global__ void round4_kernel(const float4* __restrict__ in, float4* __restrict__ out, int n4) {
    int i = blockIdx.x * blockDim.x + threadIdx.x;
    if (i < n4) {
        float4 v = in[i];
        v.x = rna_tf32(v.x); v.y = rna_tf32(v.y); v.z = rna_tf32(v.z); v.w = rna_tf32(v.w);
        out[i] = v;
    }
}
__global__ void transpose_w_kernel(const float* __restrict__ W, float* __restrict__ WT,
                                   int K, int N) {
    __shared__ float t[32][33];
    const int kb = blockIdx.x * 32, nb = blockIdx.y * 32;
    const int tx = threadIdx.x, ty = threadIdx.y;
    for (int i = ty; i < 32; i += 8)
        t[i][tx] = W[(size_t)(kb + i) * N + nb + tx];
    __syncthreads();
    for (int i = ty; i < 32; i += 8)
        WT[(size_t)(nb + i) * K + kb + tx] = rna_tf32(t[tx][i]);
}

// ---------------------------------------------------------------------------
// Attention (fp32 flash); output rounded to tf32
// ---------------------------------------------------------------------------
__global__ __launch_bounds__(256) void attn_kernel(
    const float* __restrict__ q, const float* __restrict__ k,
    const float* __restrict__ v, const float* __restrict__ mask,
    float* __restrict__ out)
{
    __shared__ float ks[128][36];
    __shared__ float vs[128][36];

    const int bx = blockIdx.x;
    const int g  = bx >> 3;
    const int h  = bx & 7;
    const long base = (long)g * N_SEQ;
    const int hoff = h * DK;
    const int n12 = g & 15;
    const int tid = threadIdx.x;

    float qr[DK];
    {
        const float* qp = q + (base + tid) * E_DIM + hoff;
#pragma unroll
        for (int d = 0; d < DK; d += 4)
            *(float4*)&qr[d] = *(const float4*)(qp + d);
    }
    const float* mrow = mask + ((long)n12 * N_SEQ + tid) * N_SEQ;

    float m = -1e30f, l = 0.f;
    float acc[DK];
#pragma unroll
    for (int d = 0; d < DK; d++) acc[d] = 0.f;

    for (int c = 0; c < 2; c++) {
        __syncthreads();
        {
            const int r = tid & 127;
            const float* src = ((tid < 128) ? k : v) + (base + c * 128 + r) * E_DIM + hoff;
            float (*dst)[36] = (tid < 128) ? ks : vs;
#pragma unroll
            for (int d = 0; d < DK; d += 4)
                *(float4*)&dst[r][d] = *(const float4*)(src + d);
        }
        __syncthreads();

        const float* mp = mrow + c * 128;
        for (int j = 0; j < 128; j++) {
            float s0 = 0.f, s1 = 0.f;
#pragma unroll
            for (int d = 0; d < DK; d += 2) {
                s0 = fmaf(qr[d],     ks[j][d],     s0);
                s1 = fmaf(qr[d + 1], ks[j][d + 1], s1);
            }
            float s = s0 + s1 + mp[j];
            if (s > m) {
                const float cf = __expf(m - s);
                l *= cf;
#pragma unroll
                for (int d = 0; d < DK; d++) acc[d] *= cf;
                m = s;
            }
            const float p = __expf(s - m);
            l += p;
#pragma unroll
            for (int d = 0; d < DK; d++)
                acc[d] = fmaf(p, vs[j][d], acc[d]);
        }
    }

    const float inv = 1.f / l;
    float* op = out + (base + tid) * E_DIM + hoff;
#pragma unroll
    for (int d = 0; d < DK; d += 4) {
        float4 r;
        r.x = rna_tf32(acc[d + 0] * inv); r.y = rna_tf32(acc[d + 1] * inv);
        r.z = rna_tf32(acc[d + 2] * inv); r.w = rna_tf32(acc[d + 3] * inv);
        *(float4*)(op + d) = r;
    }
}

// ---------------------------------------------------------------------------
// LayerNorm over E=256; optionally also write tf32-rounded copy
// ---------------------------------------------------------------------------
template<bool DUAL>
__global__ __launch_bounds__(256) void layernorm_kernel(
    const float* __restrict__ in, const float* __restrict__ g,
    const float* __restrict__ b, float* __restrict__ out,
    float* __restrict__ out_r)
{
    const long row = blockIdx.x;
    const int tid = threadIdx.x;
    const float vv = in[row * E_DIM + tid];

    float s = vv, sq = vv * vv;
#pragma unroll
    for (int o = 16; o; o >>= 1) {
        s  += __shfl_xor_sync(0xffffffffu, s,  o);
        sq += __shfl_xor_sync(0xffffffffu, sq, o);
    }
    __shared__ float ss[8], ssq[8];
    if ((tid & 31) == 0) { ss[tid >> 5] = s; ssq[tid >> 5] = sq; }
    __syncthreads();
    float S = 0.f, SQ = 0.f;
#pragma unroll
    for (int i = 0; i < 8; i++) { S += ss[i]; SQ += ssq[i]; }

    const float mean = S * (1.f / E_DIM);
    const float var  = SQ * (1.f / E_DIM) - mean * mean;
    const float r    = rsqrtf(var + LN_EPS);
    const float o = (vv - mean) * r * g[tid] + b[tid];
    out[row * E_DIM + tid] = o;
    if (DUAL) out_r[row * E_DIM + tid] = rna_tf32(o);
}

// ---------------------------------------------------------------------------
extern "C" void kernel_launch(void* const* d_in, const int* in_sizes, int n_in,
                              void* d_out, int out_size)
{
    const float* x     = (const float*)d_in[0];
    const float* mask  = (const float*)d_in[1];
    const float* Wq    = (const float*)d_in[2];
    const float* Wk    = (const float*)d_in[3];
    const float* Wv    = (const float*)d_in[4];
    const float* Wo    = (const float*)d_in[5];
    const float* bo    = (const float*)d_in[6];
    const float* W1    = (const float*)d_in[7];
    const float* bf1   = (const float*)d_in[8];
    const float* W2    = (const float*)d_in[9];
    const float* bf2   = (const float*)d_in[10];
    const float* g1    = (const float*)d_in[11];
    const float* beta1 = (const float*)d_in[12];
    const float* g2    = (const float*)d_in[13];
    const float* beta2 = (const float*)d_in[14];
    float* out = (float*)d_out;

    float *xr, *q, *k, *v, *attn, *y1, *h1, *h1r, *hid, *y2;
    float *WqT, *WkT, *WvT, *WoT, *W1T, *W2T;
    cudaGetSymbolAddress((void**)&xr,   g_xr);
    cudaGetSymbolAddress((void**)&q,    g_q);
    cudaGetSymbolAddress((void**)&k,    g_k);
    cudaGetSymbolAddress((void**)&v,    g_v);
    cudaGetSymbolAddress((void**)&attn, g_attn);
    cudaGetSymbolAddress((void**)&y1,   g_y1);
    cudaGetSymbolAddress((void**)&h1,   g_h1);
    cudaGetSymbolAddress((void**)&h1r,  g_h1r);
    cudaGetSymbolAddress((void**)&hid,  g_hid);
    cudaGetSymbolAddress((void**)&y2,   g_y2);
    cudaGetSymbolAddress((void**)&WqT,  g_WqT);
    cudaGetSymbolAddress((void**)&WkT,  g_WkT);
    cudaGetSymbolAddress((void**)&WvT,  g_WvT);
    cudaGetSymbolAddress((void**)&WoT,  g_WoT);
    cudaGetSymbolAddress((void**)&W1T,  g_W1T);
    cudaGetSymbolAddress((void**)&W2T,  g_W2T);

    cudaFuncSetAttribute(gemm_mma<false, false, false, false>,
                         cudaFuncAttributeMaxDynamicSharedMemorySize, GSMEM);
    cudaFuncSetAttribute(gemm_mma<true, false, true, false>,
                         cudaFuncAttributeMaxDynamicSharedMemorySize, GSMEM);
    cudaFuncSetAttribute(gemm_mma<true, true, false, true>,
                         cudaFuncAttributeMaxDynamicSharedMemorySize, GSMEM);

    const dim3 blk(256);
    const dim3 tblk(32, 8);

    // prep
    round4_kernel<<<(T_TOK * E_DIM / 4 + 255) / 256, blk>>>((const float4*)x, (float4*)xr,
                                                            T_TOK * E_DIM / 4);
    transpose_w_kernel<<<dim3(E_DIM / 32, E_DIM / 32), tblk>>>(Wq, WqT, E_DIM, E_DIM);
    transpose_w_kernel<<<dim3(E_DIM / 32, E_DIM / 32), tblk>>>(Wk, WkT, E_DIM, E_DIM);
    transpose_w_kernel<<<dim3(E_DIM / 32, E_DIM / 32), tblk>>>(Wv, WvT, E_DIM, E_DIM);
    transpose_w_kernel<<<dim3(E_DIM / 32, E_DIM / 32), tblk>>>(Wo, WoT, E_DIM, E_DIM);
    transpose_w_kernel<<<dim3(E_DIM / 32, FF_DIM / 32), tblk>>>(W1, W1T, E_DIM, FF_DIM);
    transpose_w_kernel<<<dim3(FF_DIM / 32, E_DIM / 32), tblk>>>(W2, W2T, FF_DIM, E_DIM);

    const dim3 gE(E_DIM / BN, T_TOK / BM);    // (2, 512)
    const dim3 gF(FF_DIM / BN, T_TOK / BM);   // (8, 512)

    // QKV
    gemm_mma<false, false, false, false><<<gE, blk, GSMEM>>>(xr, WqT, q, E_DIM, E_DIM, SCALING, nullptr, nullptr);
    gemm_mma<false, false, false, false><<<gE, blk, GSMEM>>>(xr, WkT, k, E_DIM, E_DIM, 1.f, nullptr, nullptr);
    gemm_mma<false, false, false, false><<<gE, blk, GSMEM>>>(xr, WvT, v, E_DIM, E_DIM, 1.f, nullptr, nullptr);

    // attention
    attn_kernel<<<2048, blk>>>(q, k, v, mask, attn);

    // y1 = x + attn @ Wo + bo ; h1 = LN1(y1), h1r = round(h1)
    gemm_mma<true, false, true, false><<<gE, blk, GSMEM>>>(attn, WoT, y1, E_DIM, E_DIM, 1.f, bo, x);
    layernorm_kernel<true><<<T_TOK, blk>>>(y1, g1, beta1, h1, h1r);

    // hid = round(relu(h1r @ W1 + bf1))
    gemm_mma<true, true, false, true><<<gF, blk, GSMEM>>>(h1r, W1T, hid, FF_DIM, E_DIM, 1.f, bf1, nullptr);

    // y2 = h1 + hid @ W2 + bf2 ; out = LN2(y2)
    gemm_mma<true, false, true, false><<<gE, blk, GSMEM>>>(hid, W2T, y2, E_DIM, FF_DIM, 1.f, bf2, h1);
    layernorm_kernel<false><<<T_TOK, blk>>>(y2, g2, beta2, out, nullptr);
}

// round 4
// speedup vs baseline: 3.1339x; 1.6055x over previous
#include <cuda_runtime.h>
#include <cstdint>

// ---------------------------------------------------------------------------
// EncoderLayer: B=16, N1=4, N2=4, N=256, E=256, H=8, DK=32
// T = 65536 tokens, E = 256, FF = 1024
// GEMMs + attention on mma.sync tf32 (m16n8k8) + cp.async + ldmatrix.
// ---------------------------------------------------------------------------

#define T_TOK  65536
#define E_DIM  256
#define FF_DIM 1024
#define N_SEQ  256
#define DK     32
#define SCALING 0.17677669529663687f
#define LN_EPS 1e-5f

// ---------------- scratch (device globals; no allocs allowed) --------------
__device__ float g_xr  [T_TOK * E_DIM];
__device__ float g_q   [T_TOK * E_DIM];
__device__ float g_k   [T_TOK * E_DIM];
__device__ float g_v   [T_TOK * E_DIM];
__device__ float g_attn[T_TOK * E_DIM];
__device__ float g_y1  [T_TOK * E_DIM];
__device__ float g_h1  [T_TOK * E_DIM];
__device__ float g_h1r [T_TOK * E_DIM];
__device__ float g_hid [T_TOK * FF_DIM];
__device__ float g_y2  [T_TOK * E_DIM];
__device__ float g_WqT [E_DIM * E_DIM];
__device__ float g_WkT [E_DIM * E_DIM];
__device__ float g_WvT [E_DIM * E_DIM];
__device__ float g_WoT [E_DIM * E_DIM];
__device__ float g_W1T [FF_DIM * E_DIM];
__device__ float g_W2T [E_DIM * FF_DIM];

// ---------------- helpers ---------------------------------------------------
__device__ __forceinline__ uint32_t s2u(const void* p) {
    uint32_t a;
    asm("{ .reg .u64 t; cvta.to.shared.u64 t, %1; cvt.u32.u64 %0, t; }" : "=r"(a) : "l"(p));
    return a;
}
__device__ __forceinline__ float rna_tf32(float x) {
    uint32_t u;
    asm("cvt.rna.tf32.f32 %0, %1;" : "=r"(u) : "f"(x));
    return __uint_as_float(u);
}
__device__ __forceinline__ uint32_t rna_tf32_u(float x) {
    uint32_t u;
    asm("cvt.rna.tf32.f32 %0, %1;" : "=r"(u) : "f"(x));
    return u;
}
#define SWZ(o) ((o) ^ (((o) >> 3) & 0x70))

__device__ __forceinline__ void cpa16(uint32_t s, const void* g) {
    asm volatile("cp.async.cg.shared.global [%0], [%1], 16;" :: "r"(s), "l"(g));
}
#define CP_COMMIT() asm volatile("cp.async.commit_group;" ::: "memory")

__device__ __forceinline__ void ldsm4(uint32_t addr, uint32_t* r) {
    asm volatile("ldmatrix.sync.aligned.m8n8.x4.shared.b16 {%0,%1,%2,%3}, [%4];"
                 : "=r"(r[0]), "=r"(r[1]), "=r"(r[2]), "=r"(r[3]) : "r"(addr));
}
__device__ __forceinline__ void mma8(float* c, const uint32_t* a, const uint32_t* b) {
    asm volatile("mma.sync.aligned.m16n8k8.row.col.f32.tf32.tf32.f32 "
                 "{%0,%1,%2,%3}, {%4,%5,%6,%7}, {%8,%9}, {%0,%1,%2,%3};"
                 : "+f"(c[0]), "+f"(c[1]), "+f"(c[2]), "+f"(c[3])
                 : "r"(a[0]), "r"(a[1]), "r"(a[2]), "r"(a[3]), "r"(b[0]), "r"(b[1]));
}

// ---------------------------------------------------------------------------
// GEMM: C[M,Nt] = act(alpha * A[M,Kt] @ BT[Nt,Kt]^T + bias + resid)
// CTA 128x128, BK=32, 3-stage cp.async, 8 warps (4m x 2n), warp 32x64.
// ---------------------------------------------------------------------------
#define BM 128
#define BN 128
#define BK 32
#define STG 3
#define ASZ (BM * BK * 4)
#define BSZ (BN * BK * 4)
#define STGB (ASZ + BSZ)
#define GSMEM (STG * STGB)

template<bool BIAS, bool RELU, bool RES, bool ROUND>
__global__ __launch_bounds__(256, 1) void gemm_mma(
    const float* __restrict__ A, const float* __restrict__ BT,
    float* __restrict__ C, int Nt, int Kt, float alpha,
    const float* __restrict__ bias, const float* __restrict__ resid)
{
    extern __shared__ char smem[];
    const uint32_t sb = s2u(smem);
    const int tid = threadIdx.x;
    const int lane = tid & 31;
    const int wid = tid >> 5;
    const int wm = wid & 3;
    const int wn = wid >> 2;

    const int m0 = blockIdx.y * BM;
    const int n0 = blockIdx.x * BN;
    const float* Ag = A + (size_t)m0 * Kt;
    const float* Bg = BT + (size_t)n0 * Kt;
    const int nC = Kt / BK;

    auto load_stage = [&](int s, int c) {
        const uint32_t ab = sb + s * STGB;
        const uint32_t bb = ab + ASZ;
        const float* Ac = Ag + c * BK;
        const float* Bc = Bg + c * BK;
#pragma unroll
        for (int i = 0; i < 4; i++) {
            int g = i * 256 + tid, r = g >> 3, cc = g & 7;
            cpa16(ab + SWZ(r * 128 + cc * 16), Ac + (size_t)r * Kt + cc * 4);
        }
#pragma unroll
        for (int i = 0; i < 4; i++) {
            int g = i * 256 + tid, r = g >> 3, cc = g & 7;
            cpa16(bb + SWZ(r * 128 + cc * 16), Bc + (size_t)r * Kt + cc * 4);
        }
    };

    load_stage(0, 0);
    CP_COMMIT();
    load_stage(1, 1);
    CP_COMMIT();

    float acc[2][8][4];
#pragma unroll
    for (int tm = 0; tm < 2; tm++)
#pragma unroll
        for (int j = 0; j < 8; j++)
#pragma unroll
            for (int e = 0; e < 4; e++) acc[tm][j][e] = 0.f;

    const int a_row = wm * 32 + (lane & 15);
    const int a_cb  = (lane >> 4) * 16;
    const int b_row = wn * 64 + (lane & 7) + ((lane >> 4) << 3);
    const int b_cb  = ((lane >> 3) & 1) * 16;

    for (int c = 0; c < nC; c++) {
        const int s = c % STG;
        asm volatile("cp.async.wait_group 1;" ::: "memory");
        __syncthreads();
        const uint32_t ab = sb + s * STGB;
        const uint32_t bb = ab + ASZ;
#pragma unroll
        for (int k8 = 0; k8 < 4; k8++) {
            uint32_t afr[2][4], bfr[8][2];
#pragma unroll
            for (int tm = 0; tm < 2; tm++)
                ldsm4(ab + SWZ((a_row + tm * 16) * 128 + k8 * 32 + a_cb), afr[tm]);
#pragma unroll
            for (int p = 0; p < 4; p++) {
                uint32_t r[4];
                ldsm4(bb + SWZ((b_row + p * 16) * 128 + k8 * 32 + b_cb), r);
                bfr[2 * p][0] = r[0]; bfr[2 * p][1] = r[1];
                bfr[2 * p + 1][0] = r[2]; bfr[2 * p + 1][1] = r[3];
            }
#pragma unroll
            for (int tm = 0; tm < 2; tm++)
#pragma unroll
                for (int j = 0; j < 8; j++)
                    mma8(acc[tm][j], afr[tm], bfr[j]);
        }
        __syncthreads();
        const int cn = c + STG - 1;
        if (cn < nC) load_stage(cn % STG, cn);
        CP_COMMIT();
    }

    const int mrow = m0 + wm * 32 + (lane >> 2);
    const int ncol = n0 + wn * 64 + (lane & 3) * 2;
#pragma unroll
    for (int tm = 0; tm < 2; tm++) {
#pragma unroll
        for (int j = 0; j < 8; j++) {
            const int gc = ncol + j * 8;
#pragma unroll
            for (int h = 0; h < 2; h++) {
                const int gr = mrow + tm * 16 + h * 8;
                float v0 = acc[tm][j][2 * h + 0] * alpha;
                float v1 = acc[tm][j][2 * h + 1] * alpha;
                if (BIAS) {
                    const float2 bb = *(const float2*)(bias + gc);
                    v0 += bb.x; v1 += bb.y;
                }
                if (RES) {
                    const float2 rr = *(const float2*)(resid + (size_t)gr * Nt + gc);
                    v0 += rr.x; v1 += rr.y;
                }
                if (RELU) { v0 = fmaxf(v0, 0.f); v1 = fmaxf(v1, 0.f); }
                if (ROUND) { v0 = rna_tf32(v0); v1 = rna_tf32(v1); }
                *(float2*)(C + (size_t)gr * Nt + gc) = make_float2(v0, v1);
            }
        }
    }
}

// ---------------------------------------------------------------------------
// Prep kernels
// ---------------------------------------------------------------------------
__global__ void round4_kernel(const float4* __restrict__ in, float4* __restrict__ out, int n4) {
    int i = blockIdx.x * blockDim.x + threadIdx.x;
    if (i < n4) {
        float4 v = in[i];
        v.x = rna_tf32(v.x); v.y = rna_tf32(v.y); v.z = rna_tf32(v.z); v.w = rna_tf32(v.w);
        out[i] = v;
    }
}
__global__ void transpose_w_kernel(const float* __restrict__ W, float* __restrict__ WT,
                                   int K, int N) {
    __shared__ float t[32][33];
    const int kb = blockIdx.x * 32, nb = blockIdx.y * 32;
    const int tx = threadIdx.x, ty = threadIdx.y;
    for (int i = ty; i < 32; i += 8)
        t[i][tx] = W[(size_t)(kb + i) * N + nb + tx];
    __syncthreads();
    for (int i = ty; i < 32; i += 8)
        WT[(size_t)(nb + i) * K + kb + tx] = rna_tf32(t[tx][i]);
}

// ---------------------------------------------------------------------------
// Tensor-core flash attention. One CTA per (group, head). 8 warps, 256 thr.
// SMEM: Q[256x32] swz, K[256x32] swz, VT[32][260], P per-warp [32][68].
// ---------------------------------------------------------------------------
#define AT_Q   0
#define AT_K   32768
#define AT_VT  65536                 // 32 * 260 * 4 = 33280
#define AT_P   98816                 // 8 warps * 8704
#define AT_SMEM (AT_P + 8 * 8704)    // 168448

__global__ __launch_bounds__(256, 1) void attn_tc(
    const float* __restrict__ q, const float* __restrict__ k,
    const float* __restrict__ v, const float* __restrict__ mask,
    float* __restrict__ out)
{
    extern __shared__ char smem[];
    const uint32_t sb = s2u(smem);
    float* smf = (float*)smem;

    const int bx = blockIdx.x;
    const int g  = bx >> 3;
    const int h  = bx & 7;
    const long base = (long)g * N_SEQ;
    const int hoff = h * DK;
    const int n12 = g & 15;
    const int tid = threadIdx.x;
    const int lane = tid & 31;
    const int wid = tid >> 5;

    // stage Q, K, V (V into P region) — 2048 16B granules each
#pragma unroll
    for (int t = 0; t < 8; t++) {
        const int idx = t * 256 + tid;
        const int row = idx >> 3, cg = idx & 7;
        const long src = (base + row) * E_DIM + hoff + cg * 4;
        cpa16(sb + AT_Q + SWZ(row * 128 + cg * 16), q + src);
        cpa16(sb + AT_K + SWZ(row * 128 + cg * 16), k + src);
        cpa16(sb + AT_P + SWZ(row * 128 + cg * 16), v + src);
    }
    CP_COMMIT();
    asm volatile("cp.async.wait_group 0;" ::: "memory");
    __syncthreads();

    // transpose V: Vsm[key][d] (in P region) -> VT[d][key], rows padded to 260
#pragma unroll
    for (int t = 0; t < 8; t++) {
        const int idx = t * 256 + tid;
        const int key = idx >> 3, dg = idx & 7;
        float4 vv = *(const float4*)(smem + AT_P + SWZ(key * 128 + dg * 16));
        float* vt = smf + AT_VT / 4;
        vt[(dg * 4 + 0) * 260 + key] = vv.x;
        vt[(dg * 4 + 1) * 260 + key] = vv.y;
        vt[(dg * 4 + 2) * 260 + key] = vv.z;
        vt[(dg * 4 + 3) * 260 + key] = vv.w;
    }
    __syncthreads();

    // Q fragments (warp rows wid*32 .. +31)
    const int a_sub = lane & 15;
    const int a_cb  = (lane >> 4) * 16;
    uint32_t qfr[2][4][4];
#pragma unroll
    for (int tm = 0; tm < 2; tm++)
#pragma unroll
        for (int k8 = 0; k8 < 4; k8++)
            ldsm4(sb + AT_Q + SWZ((wid * 32 + tm * 16 + a_sub) * 128 + k8 * 32 + a_cb),
                  qfr[tm][k8]);

    const int b_sub = (lane & 7) + ((lane >> 4) << 3);
    const int b_cb  = ((lane >> 3) & 1) * 16;

    float m_[2][2], l_[2][2], accpv[2][4][4];
#pragma unroll
    for (int tm = 0; tm < 2; tm++)
#pragma unroll
        for (int hh = 0; hh < 2; hh++) { m_[tm][hh] = -1e30f; l_[tm][hh] = 0.f; }
#pragma unroll
    for (int tm = 0; tm < 2; tm++)
#pragma unroll
        for (int jn = 0; jn < 4; jn++)
#pragma unroll
            for (int e = 0; e < 4; e++) accpv[tm][jn][e] = 0.f;

    const uint32_t pw = sb + AT_P + wid * 8704;
    const int r4 = lane >> 2;            // row within 8-row group
    const int c2 = (lane & 3) * 2;       // col pair base

    for (int ch = 0; ch < 4; ch++) {
        // ---- S = Q @ K^T for 64-key chunk ----
        float accS[2][8][4];
#pragma unroll
        for (int tm = 0; tm < 2; tm++)
#pragma unroll
            for (int j = 0; j < 8; j++)
#pragma unroll
                for (int e = 0; e < 4; e++) accS[tm][j][e] = 0.f;

#pragma unroll
        for (int k8 = 0; k8 < 4; k8++) {
            uint32_t bfr[8][2];
#pragma unroll
            for (int p = 0; p < 4; p++) {
                uint32_t r[4];
                ldsm4(sb + AT_K + SWZ((ch * 64 + p * 16 + b_sub) * 128 + k8 * 32 + b_cb), r);
                bfr[2 * p][0] = r[0]; bfr[2 * p][1] = r[1];
                bfr[2 * p + 1][0] = r[2]; bfr[2 * p + 1][1] = r[3];
            }
#pragma unroll
            for (int tm = 0; tm < 2; tm++)
#pragma unroll
                for (int j = 0; j < 8; j++)
                    mma8(accS[tm][j], qfr[tm][k8], bfr[j]);
        }

        // ---- add mask (fp32) ----
#pragma unroll
        for (int tm = 0; tm < 2; tm++)
#pragma unroll
            for (int hh = 0; hh < 2; hh++) {
                const int grow = wid * 32 + r4 + tm * 16 + hh * 8;
                const float* mp = mask + ((size_t)(n12 * N_SEQ + grow)) * N_SEQ + ch * 64 + c2;
#pragma unroll
                for (int j = 0; j < 8; j++) {
                    const float2 mm = *(const float2*)(mp + j * 8);
                    accS[tm][j][2 * hh + 0] += mm.x;
                    accS[tm][j][2 * hh + 1] += mm.y;
                }
            }

        // ---- online softmax ----
#pragma unroll
        for (int tm = 0; tm < 2; tm++)
#pragma unroll
            for (int hh = 0; hh < 2; hh++) {
                float mx = -1e30f;
#pragma unroll
                for (int j = 0; j < 8; j++) {
                    mx = fmaxf(mx, accS[tm][j][2 * hh + 0]);
                    mx = fmaxf(mx, accS[tm][j][2 * hh + 1]);
                }
                mx = fmaxf(mx, __shfl_xor_sync(0xffffffffu, mx, 1));
                mx = fmaxf(mx, __shfl_xor_sync(0xffffffffu, mx, 2));
                const float mnew = fmaxf(m_[tm][hh], mx);
                const float sc = __expf(m_[tm][hh] - mnew);
                m_[tm][hh] = mnew;
                l_[tm][hh] *= sc;
#pragma unroll
                for (int jn = 0; jn < 4; jn++) {
                    accpv[tm][jn][2 * hh + 0] *= sc;
                    accpv[tm][jn][2 * hh + 1] *= sc;
                }
                // p = exp(s - mnew), accumulate row sum, store tf32 p
                float rs = 0.f;
#pragma unroll
                for (int j = 0; j < 8; j++) {
                    const float p0 = __expf(accS[tm][j][2 * hh + 0] - mnew);
                    const float p1 = __expf(accS[tm][j][2 * hh + 1] - mnew);
                    rs += p0 + p1;
                    const int prow = r4 + tm * 16 + hh * 8;
                    uint32_t* pp = (uint32_t*)(smem + (pw - sb)) + prow * 68 + c2 + j * 8;
                    pp[0] = rna_tf32_u(p0);
                    pp[1] = rna_tf32_u(p1);
                }
                rs += __shfl_xor_sync(0xffffffffu, rs, 1);
                rs += __shfl_xor_sync(0xffffffffu, rs, 2);
                l_[tm][hh] += rs;
            }
        __syncwarp();

        // ---- PV: accpv += P(32x64) @ V(64x32) ----
#pragma unroll
        for (int k8 = 0; k8 < 8; k8++) {
            uint32_t afrP[2][4];
#pragma unroll
            for (int tm = 0; tm < 2; tm++)
                ldsm4(pw + (tm * 16 + a_sub) * 272 + k8 * 32 + a_cb, afrP[tm]);
            uint32_t bfrV[4][2];
#pragma unroll
            for (int p = 0; p < 2; p++) {
                uint32_t r[4];
                ldsm4(sb + AT_VT + (p * 16 + b_sub) * 1040 + ch * 256 + k8 * 32 + b_cb, r);
                bfrV[2 * p][0] = r[0]; bfrV[2 * p][1] = r[1];
                bfrV[2 * p + 1][0] = r[2]; bfrV[2 * p + 1][1] = r[3];
            }
#pragma unroll
            for (int tm = 0; tm < 2; tm++)
#pragma unroll
                for (int jn = 0; jn < 4; jn++)
                    mma8(accpv[tm][jn], afrP[tm], bfrV[jn]);
        }
        __syncwarp();
    }

    // ---- epilogue: out = accpv / l, rounded to tf32 ----
#pragma unroll
    for (int tm = 0; tm < 2; tm++)
#pragma unroll
        for (int hh = 0; hh < 2; hh++) {
            const float inv = 1.f / l_[tm][hh];
            const long row = base + wid * 32 + r4 + tm * 16 + hh * 8;
            float* op = out + row * E_DIM + hoff + c2;
#pragma unroll
            for (int jn = 0; jn < 4; jn++) {
                float2 o;
                o.x = rna_tf32(accpv[tm][jn][2 * hh + 0] * inv);
                o.y = rna_tf32(accpv[tm][jn][2 * hh + 1] * inv);
                *(float2*)(op + jn * 8) = o;
            }
        }
}

// ---------------------------------------------------------------------------
// LayerNorm over E=256; optionally also write tf32-rounded copy
// ---------------------------------------------------------------------------
template<bool DUAL>
__global__ __launch_bounds__(256) void layernorm_kernel(
    const float* __restrict__ in, const float* __restrict__ g,
    const float* __restrict__ b, float* __restrict__ out,
    float* __restrict__ out_r)
{
    const long row = blockIdx.x;
    const int tid = threadIdx.x;
    const float vv = in[row * E_DIM + tid];

    float s = vv, sq = vv * vv;
#pragma unroll
    for (int o = 16; o; o >>= 1) {
        s  += __shfl_xor_sync(0xffffffffu, s,  o);
        sq += __shfl_xor_sync(0xffffffffu, sq, o);
    }
    __shared__ float ss[8], ssq[8];
    if ((tid & 31) == 0) { ss[tid >> 5] = s; ssq[tid >> 5] = sq; }
    __syncthreads();
    float S = 0.f, SQ = 0.f;
#pragma unroll
    for (int i = 0; i < 8; i++) { S += ss[i]; SQ += ssq[i]; }

    const float mean = S * (1.f / E_DIM);
    const float var  = SQ * (1.f / E_DIM) - mean * mean;
    const float r    = rsqrtf(var + LN_EPS);
    const float o = (vv - mean) * r * g[tid] + b[tid];
    out[row * E_DIM + tid] = o;
    if (DUAL) out_r[row * E_DIM + tid] = rna_tf32(o);
}

// ---------------------------------------------------------------------------
extern "C" void kernel_launch(void* const* d_in, const int* in_sizes, int n_in,
                              void* d_out, int out_size)
{
    const float* x     = (const float*)d_in[0];
    const float* mask  = (const float*)d_in[1];
    const float* Wq    = (const float*)d_in[2];
    const float* Wk    = (const float*)d_in[3];
    const float* Wv    = (const float*)d_in[4];
    const float* Wo    = (const float*)d_in[5];
    const float* bo    = (const float*)d_in[6];
    const float* W1    = (const float*)d_in[7];
    const float* bf1   = (const float*)d_in[8];
    const float* W2    = (const float*)d_in[9];
    const float* bf2   = (const float*)d_in[10];
    const float* g1    = (const float*)d_in[11];
    const float* beta1 = (const float*)d_in[12];
    const float* g2    = (const float*)d_in[13];
    const float* beta2 = (const float*)d_in[14];
    float* out = (float*)d_out;

    float *xr, *q, *k, *v, *attn, *y1, *h1, *h1r, *hid, *y2;
    float *WqT, *WkT, *WvT, *WoT, *W1T, *W2T;
    cudaGetSymbolAddress((void**)&xr,   g_xr);
    cudaGetSymbolAddress((void**)&q,    g_q);
    cudaGetSymbolAddress((void**)&k,    g_k);
    cudaGetSymbolAddress((void**)&v,    g_v);
    cudaGetSymbolAddress((void**)&attn, g_attn);
    cudaGetSymbolAddress((void**)&y1,   g_y1);
    cudaGetSymbolAddress((void**)&h1,   g_h1);
    cudaGetSymbolAddress((void**)&h1r,  g_h1r);
    cudaGetSymbolAddress((void**)&hid,  g_hid);
    cudaGetSymbolAddress((void**)&y2,   g_y2);
    cudaGetSymbolAddress((void**)&WqT,  g_WqT);
    cudaGetSymbolAddress((void**)&WkT,  g_WkT);
    cudaGetSymbolAddress((void**)&WvT,  g_WvT);
    cudaGetSymbolAddress((void**)&WoT,  g_WoT);
    cudaGetSymbolAddress((void**)&W1T,  g_W1T);
    cudaGetSymbolAddress((void**)&W2T,  g_W2T);

    cudaFuncSetAttribute(gemm_mma<false, false, false, true>,
                         cudaFuncAttributeMaxDynamicSharedMemorySize, GSMEM);
    cudaFuncSetAttribute(gemm_mma<true, false, true, false>,
                         cudaFuncAttributeMaxDynamicSharedMemorySize, GSMEM);
    cudaFuncSetAttribute(gemm_mma<true, true, false, true>,
                         cudaFuncAttributeMaxDynamicSharedMemorySize, GSMEM);
    cudaFuncSetAttribute(attn_tc,
                         cudaFuncAttributeMaxDynamicSharedMemorySize, AT_SMEM);

    const dim3 blk(256);
    const dim3 tblk(32, 8);

    // prep
    round4_kernel<<<(T_TOK * E_DIM / 4 + 255) / 256, blk>>>((const float4*)x, (float4*)xr,
                                                            T_TOK * E_DIM / 4);
    transpose_w_kernel<<<dim3(E_DIM / 32, E_DIM / 32), tblk>>>(Wq, WqT, E_DIM, E_DIM);
    transpose_w_kernel<<<dim3(E_DIM / 32, E_DIM / 32), tblk>>>(Wk, WkT, E_DIM, E_DIM);
    transpose_w_kernel<<<dim3(E_DIM / 32, E_DIM / 32), tblk>>>(Wv, WvT, E_DIM, E_DIM);
    transpose_w_kernel<<<dim3(E_DIM / 32, E_DIM / 32), tblk>>>(Wo, WoT, E_DIM, E_DIM);
    transpose_w_kernel<<<dim3(E_DIM / 32, FF_DIM / 32), tblk>>>(W1, W1T, E_DIM, FF_DIM);
    transpose_w_kernel<<<dim3(FF_DIM / 32, E_DIM / 32), tblk>>>(W2, W2T, FF_DIM, E_DIM);

    const dim3 gE(E_DIM / BN, T_TOK / BM);
    const dim3 gF(FF_DIM / BN, T_TOK / BM);

    // QKV (tf32-rounded outputs feed tensor-core attention)
    gemm_mma<false, false, false, true><<<gE, blk, GSMEM>>>(xr, WqT, q, E_DIM, E_DIM, SCALING, nullptr, nullptr);
    gemm_mma<false, false, false, true><<<gE, blk, GSMEM>>>(xr, WkT, k, E_DIM, E_DIM, 1.f, nullptr, nullptr);
    gemm_mma<false, false, false, true><<<gE, blk, GSMEM>>>(xr, WvT, v, E_DIM, E_DIM, 1.f, nullptr, nullptr);

    // attention (tensor cores)
    attn_tc<<<2048, blk, AT_SMEM>>>(q, k, v, mask, attn);

    // y1 = x + attn @ Wo + bo ; h1 = LN1(y1), h1r = round(h1)
    gemm_mma<true, false, true, false><<<gE, blk, GSMEM>>>(attn, WoT, y1, E_DIM, E_DIM, 1.f, bo, x);
    layernorm_kernel<true><<<T_TOK, blk>>>(y1, g1, beta1, h1, h1r);

    // hid = round(relu(h1r @ W1 + bf1))
    gemm_mma<true, true, false, true><<<gF, blk, GSMEM>>>(h1r, W1T, hid, FF_DIM, E_DIM, 1.f, bf1, nullptr);

    // y2 = h1 + hid @ W2 + bf2 ; out = LN2(y2)
    gemm_mma<true, false, true, false><<<gE, blk, GSMEM>>>(hid, W2T, y2, E_DIM, FF_DIM, 1.f, bf2, h1);
    layernorm_kernel<false><<<T_TOK, blk>>>(y2, g2, beta2, out, nullptr);
}

// round 5
// speedup vs baseline: 3.5679x; 1.1385x over previous
#include <cuda_runtime.h>
#include <cstdint>

// ---------------------------------------------------------------------------
// EncoderLayer: B=16, N1=4, N2=4, N=256, E=256, H=8, DK=32
// T = 65536 tokens, E = 256, FF = 1024
// GEMMs + attention on mma.sync tf32 (m16n8k8) + cp.async + ldmatrix.
// ---------------------------------------------------------------------------

#define T_TOK  65536
#define E_DIM  256
#define FF_DIM 1024
#define N_SEQ  256
#define DK     32
#define SCALING 0.17677669529663687f
#define LN_EPS 1e-5f

// ---------------- scratch (device globals; no allocs allowed) --------------
__device__ float g_xr   [T_TOK * E_DIM];
__device__ float g_qkv  [T_TOK * 3 * E_DIM];
__device__ float g_attn [T_TOK * E_DIM];
__device__ float g_y1   [T_TOK * E_DIM];
__device__ float g_h1   [T_TOK * E_DIM];
__device__ float g_h1r  [T_TOK * E_DIM];
__device__ float g_hid  [T_TOK * FF_DIM];
__device__ float g_y2   [T_TOK * E_DIM];
__device__ float g_WqkvT[3 * E_DIM * E_DIM];
__device__ float g_WoT  [E_DIM * E_DIM];
__device__ float g_W1T  [FF_DIM * E_DIM];
__device__ float g_W2T  [E_DIM * FF_DIM];

// ---------------- helpers ---------------------------------------------------
__device__ __forceinline__ uint32_t s2u(const void* p) {
    uint32_t a;
    asm("{ .reg .u64 t; cvta.to.shared.u64 t, %1; cvt.u32.u64 %0, t; }" : "=r"(a) : "l"(p));
    return a;
}
__device__ __forceinline__ float rna_tf32(float x) {
    uint32_t u;
    asm("cvt.rna.tf32.f32 %0, %1;" : "=r"(u) : "f"(x));
    return __uint_as_float(u);
}
__device__ __forceinline__ uint32_t rna_tf32_u(float x) {
    uint32_t u;
    asm("cvt.rna.tf32.f32 %0, %1;" : "=r"(u) : "f"(x));
    return u;
}
#define SWZ(o)  ((o) ^ (((o) >> 3) & 0x70))   // 128B rows
#define SWZ2(o) ((o) ^ (((o) >> 4) & 0x70))   // 256B rows

__device__ __forceinline__ void cpa16(uint32_t s, const void* g) {
    asm volatile("cp.async.cg.shared.global [%0], [%1], 16;" :: "r"(s), "l"(g));
}
#define CP_COMMIT() asm volatile("cp.async.commit_group;" ::: "memory")

__device__ __forceinline__ void ldsm4(uint32_t addr, uint32_t* r) {
    asm volatile("ldmatrix.sync.aligned.m8n8.x4.shared.b16 {%0,%1,%2,%3}, [%4];"
                 : "=r"(r[0]), "=r"(r[1]), "=r"(r[2]), "=r"(r[3]) : "r"(addr));
}
__device__ __forceinline__ void mma8(float* c, const uint32_t* a, const uint32_t* b) {
    asm volatile("mma.sync.aligned.m16n8k8.row.col.f32.tf32.tf32.f32 "
                 "{%0,%1,%2,%3}, {%4,%5,%6,%7}, {%8,%9}, {%0,%1,%2,%3};"
                 : "+f"(c[0]), "+f"(c[1]), "+f"(c[2]), "+f"(c[3])
                 : "r"(a[0]), "r"(a[1]), "r"(a[2]), "r"(a[3]), "r"(b[0]), "r"(b[1]));
}

// ---------------------------------------------------------------------------
// GEMM: C[M,Nt] = act(alpha * A[M,Kt] @ BT[Nt,Kt]^T + bias + resid)
// CTA 128x128, BK=64, 3-stage cp.async, 8 warps (4m x 2n), warp 32x64.
// SMEM rows are 256B (64 tf32), swizzle SWZ2.
// ---------------------------------------------------------------------------
#define BM 128
#define BN 128
#define BK 64
#define STG 3
#define ASZ (BM * BK * 4)            // 32768
#define BSZ (BN * BK * 4)            // 32768
#define STGB (ASZ + BSZ)             // 65536
#define GSMEM (STG * STGB)           // 196608

template<bool BIAS, bool RELU, bool RES, bool ROUND>
__global__ __launch_bounds__(256, 1) void gemm_mma(
    const float* __restrict__ A, const float* __restrict__ BT,
    float* __restrict__ C, int Nt, int Kt, float alpha,
    const float* __restrict__ bias, const float* __restrict__ resid)
{
    extern __shared__ char smem[];
    const uint32_t sb = s2u(smem);
    const int tid = threadIdx.x;
    const int lane = tid & 31;
    const int wid = tid >> 5;
    const int wm = wid & 3;
    const int wn = wid >> 2;

    const int m0 = blockIdx.y * BM;
    const int n0 = blockIdx.x * BN;
    const float* Ag = A + (size_t)m0 * Kt;
    const float* Bg = BT + (size_t)n0 * Kt;
    const int nC = Kt / BK;

    auto load_stage = [&](int s, int c) {
        const uint32_t ab = sb + s * STGB;
        const uint32_t bb = ab + ASZ;
        const float* Ac = Ag + c * BK;
        const float* Bc = Bg + c * BK;
#pragma unroll
        for (int i = 0; i < 8; i++) {        // A: 128 rows x 16 granules
            int g = i * 256 + tid, r = g >> 4, cc = g & 15;
            cpa16(ab + SWZ2(r * 256 + cc * 16), Ac + (size_t)r * Kt + cc * 4);
        }
#pragma unroll
        for (int i = 0; i < 8; i++) {        // B
            int g = i * 256 + tid, r = g >> 4, cc = g & 15;
            cpa16(bb + SWZ2(r * 256 + cc * 16), Bc + (size_t)r * Kt + cc * 4);
        }
    };

    load_stage(0, 0);
    CP_COMMIT();
    if (nC > 1) load_stage(1, 1);
    CP_COMMIT();

    float acc[2][8][4];
#pragma unroll
    for (int tm = 0; tm < 2; tm++)
#pragma unroll
        for (int j = 0; j < 8; j++)
#pragma unroll
            for (int e = 0; e < 4; e++) acc[tm][j][e] = 0.f;

    const int a_row = wm * 32 + (lane & 15);
    const int a_cb  = (lane >> 4) * 16;
    const int b_row = wn * 64 + (lane & 7) + ((lane >> 4) << 3);
    const int b_cb  = ((lane >> 3) & 1) * 16;

    for (int c = 0; c < nC; c++) {
        const int s = c % STG;
        asm volatile("cp.async.wait_group 1;" ::: "memory");
        __syncthreads();
        const uint32_t ab = sb + s * STGB;
        const uint32_t bb = ab + ASZ;
#pragma unroll
        for (int k8 = 0; k8 < 8; k8++) {
            uint32_t afr[2][4], bfr[8][2];
#pragma unroll
            for (int tm = 0; tm < 2; tm++)
                ldsm4(ab + SWZ2((a_row + tm * 16) * 256 + k8 * 32 + a_cb), afr[tm]);
#pragma unroll
            for (int p = 0; p < 4; p++) {
                uint32_t r[4];
                ldsm4(bb + SWZ2((b_row + p * 16) * 256 + k8 * 32 + b_cb), r);
                bfr[2 * p][0] = r[0]; bfr[2 * p][1] = r[1];
                bfr[2 * p + 1][0] = r[2]; bfr[2 * p + 1][1] = r[3];
            }
#pragma unroll
            for (int tm = 0; tm < 2; tm++)
#pragma unroll
                for (int j = 0; j < 8; j++)
                    mma8(acc[tm][j], afr[tm], bfr[j]);
        }
        __syncthreads();
        const int cn = c + STG - 1;
        if (cn < nC) load_stage(cn % STG, cn);
        CP_COMMIT();
    }

    const int mrow = m0 + wm * 32 + (lane >> 2);
    const int ncol = n0 + wn * 64 + (lane & 3) * 2;
#pragma unroll
    for (int tm = 0; tm < 2; tm++) {
#pragma unroll
        for (int j = 0; j < 8; j++) {
            const int gc = ncol + j * 8;
#pragma unroll
            for (int h = 0; h < 2; h++) {
                const int gr = mrow + tm * 16 + h * 8;
                float v0 = acc[tm][j][2 * h + 0] * alpha;
                float v1 = acc[tm][j][2 * h + 1] * alpha;
                if (BIAS) {
                    const float2 bb = *(const float2*)(bias + gc);
                    v0 += bb.x; v1 += bb.y;
                }
                if (RES) {
                    const float2 rr = *(const float2*)(resid + (size_t)gr * Nt + gc);
                    v0 += rr.x; v1 += rr.y;
                }
                if (RELU) { v0 = fmaxf(v0, 0.f); v1 = fmaxf(v1, 0.f); }
                if (ROUND) { v0 = rna_tf32(v0); v1 = rna_tf32(v1); }
                *(float2*)(C + (size_t)gr * Nt + gc) = make_float2(v0, v1);
            }
        }
    }
}

// ---------------------------------------------------------------------------
// Prep kernels
// ---------------------------------------------------------------------------
__global__ void round4_kernel(const float4* __restrict__ in, float4* __restrict__ out, int n4) {
    int i = blockIdx.x * blockDim.x + threadIdx.x;
    if (i < n4) {
        float4 v = in[i];
        v.x = rna_tf32(v.x); v.y = rna_tf32(v.y); v.z = rna_tf32(v.z); v.w = rna_tf32(v.w);
        out[i] = v;
    }
}
__global__ void transpose_w_kernel(const float* __restrict__ W, float* __restrict__ WT,
                                   int K, int N, float scale) {
    __shared__ float t[32][33];
    const int kb = blockIdx.x * 32, nb = blockIdx.y * 32;
    const int tx = threadIdx.x, ty = threadIdx.y;
    for (int i = ty; i < 32; i += 8)
        t[i][tx] = W[(size_t)(kb + i) * N + nb + tx];
    __syncthreads();
    for (int i = ty; i < 32; i += 8)
        WT[(size_t)(nb + i) * K + kb + tx] = rna_tf32(t[tx][i] * scale);
}

// ---------------------------------------------------------------------------
// Tensor-core flash attention. One CTA per (group, head). 8 warps, 256 thr.
// qkv layout: [T, 768] (q cols 0-255, k 256-511, v 512-767).
// SMEM: Q[256x32] swz128, K[256x32] swz128, VT[32][260], P per-warp [32][68].
// ---------------------------------------------------------------------------
#define QKV_LD (3 * E_DIM)
#define AT_Q   0
#define AT_K   32768
#define AT_VT  65536
#define AT_P   98816
#define AT_SMEM (AT_P + 8 * 8704)    // 168448

__global__ __launch_bounds__(256, 1) void attn_tc(
    const float* __restrict__ qkv, const float* __restrict__ mask,
    float* __restrict__ out)
{
    extern __shared__ char smem[];
    const uint32_t sb = s2u(smem);
    float* smf = (float*)smem;

    const int bx = blockIdx.x;
    const int g  = bx >> 3;
    const int h  = bx & 7;
    const long base = (long)g * N_SEQ;
    const int hoff = h * DK;
    const int n12 = g & 15;
    const int tid = threadIdx.x;
    const int lane = tid & 31;
    const int wid = tid >> 5;

#pragma unroll
    for (int t = 0; t < 8; t++) {
        const int idx = t * 256 + tid;
        const int row = idx >> 3, cg = idx & 7;
        const long src = (base + row) * QKV_LD + hoff + cg * 4;
        cpa16(sb + AT_Q + SWZ(row * 128 + cg * 16), qkv + src);
        cpa16(sb + AT_K + SWZ(row * 128 + cg * 16), qkv + src + E_DIM);
        cpa16(sb + AT_P + SWZ(row * 128 + cg * 16), qkv + src + 2 * E_DIM);
    }
    CP_COMMIT();
    asm volatile("cp.async.wait_group 0;" ::: "memory");
    __syncthreads();

    // transpose V (in P region) -> VT[d][key], rows padded to 260 floats
#pragma unroll
    for (int t = 0; t < 8; t++) {
        const int idx = t * 256 + tid;
        const int key = idx >> 3, dg = idx & 7;
        float4 vv = *(const float4*)(smem + AT_P + SWZ(key * 128 + dg * 16));
        float* vt = smf + AT_VT / 4;
        vt[(dg * 4 + 0) * 260 + key] = vv.x;
        vt[(dg * 4 + 1) * 260 + key] = vv.y;
        vt[(dg * 4 + 2) * 260 + key] = vv.z;
        vt[(dg * 4 + 3) * 260 + key] = vv.w;
    }
    __syncthreads();

    const int a_sub = lane & 15;
    const int a_cb  = (lane >> 4) * 16;
    uint32_t qfr[2][4][4];
#pragma unroll
    for (int tm = 0; tm < 2; tm++)
#pragma unroll
        for (int k8 = 0; k8 < 4; k8++)
            ldsm4(sb + AT_Q + SWZ((wid * 32 + tm * 16 + a_sub) * 128 + k8 * 32 + a_cb),
                  qfr[tm][k8]);

    const int b_sub = (lane & 7) + ((lane >> 4) << 3);
    const int b_cb  = ((lane >> 3) & 1) * 16;

    float m_[2][2], l_[2][2], accpv[2][4][4];
#pragma unroll
    for (int tm = 0; tm < 2; tm++)
#pragma unroll
        for (int hh = 0; hh < 2; hh++) { m_[tm][hh] = -1e30f; l_[tm][hh] = 0.f; }
#pragma unroll
    for (int tm = 0; tm < 2; tm++)
#pragma unroll
        for (int jn = 0; jn < 4; jn++)
#pragma unroll
            for (int e = 0; e < 4; e++) accpv[tm][jn][e] = 0.f;

    const uint32_t pw = sb + AT_P + wid * 8704;
    const int r4 = lane >> 2;
    const int c2 = (lane & 3) * 2;

    for (int ch = 0; ch < 4; ch++) {
        float accS[2][8][4];
#pragma unroll
        for (int tm = 0; tm < 2; tm++)
#pragma unroll
            for (int j = 0; j < 8; j++)
#pragma unroll
                for (int e = 0; e < 4; e++) accS[tm][j][e] = 0.f;

#pragma unroll
        for (int k8 = 0; k8 < 4; k8++) {
            uint32_t bfr[8][2];
#pragma unroll
            for (int p = 0; p < 4; p++) {
                uint32_t r[4];
                ldsm4(sb + AT_K + SWZ((ch * 64 + p * 16 + b_sub) * 128 + k8 * 32 + b_cb), r);
                bfr[2 * p][0] = r[0]; bfr[2 * p][1] = r[1];
                bfr[2 * p + 1][0] = r[2]; bfr[2 * p + 1][1] = r[3];
            }
#pragma unroll
            for (int tm = 0; tm < 2; tm++)
#pragma unroll
                for (int j = 0; j < 8; j++)
                    mma8(accS[tm][j], qfr[tm][k8], bfr[j]);
        }

#pragma unroll
        for (int tm = 0; tm < 2; tm++)
#pragma unroll
            for (int hh = 0; hh < 2; hh++) {
                const int grow = wid * 32 + r4 + tm * 16 + hh * 8;
                const float* mp = mask + ((size_t)(n12 * N_SEQ + grow)) * N_SEQ + ch * 64 + c2;
#pragma unroll
                for (int j = 0; j < 8; j++) {
                    const float2 mm = *(const float2*)(mp + j * 8);
                    accS[tm][j][2 * hh + 0] += mm.x;
                    accS[tm][j][2 * hh + 1] += mm.y;
                }
            }

#pragma unroll
        for (int tm = 0; tm < 2; tm++)
#pragma unroll
            for (int hh = 0; hh < 2; hh++) {
                float mx = -1e30f;
#pragma unroll
                for (int j = 0; j < 8; j++) {
                    mx = fmaxf(mx, accS[tm][j][2 * hh + 0]);
                    mx = fmaxf(mx, accS[tm][j][2 * hh + 1]);
                }
                mx = fmaxf(mx, __shfl_xor_sync(0xffffffffu, mx, 1));
                mx = fmaxf(mx, __shfl_xor_sync(0xffffffffu, mx, 2));
                const float mnew = fmaxf(m_[tm][hh], mx);
                const float sc = __expf(m_[tm][hh] - mnew);
                m_[tm][hh] = mnew;
                l_[tm][hh] *= sc;
#pragma unroll
                for (int jn = 0; jn < 4; jn++) {
                    accpv[tm][jn][2 * hh + 0] *= sc;
                    accpv[tm][jn][2 * hh + 1] *= sc;
                }
                float rs = 0.f;
#pragma unroll
                for (int j = 0; j < 8; j++) {
                    const float p0 = __expf(accS[tm][j][2 * hh + 0] - mnew);
                    const float p1 = __expf(accS[tm][j][2 * hh + 1] - mnew);
                    rs += p0 + p1;
                    const int prow = r4 + tm * 16 + hh * 8;
                    uint32_t* pp = (uint32_t*)(smem + (pw - sb)) + prow * 68 + c2 + j * 8;
                    pp[0] = rna_tf32_u(p0);
                    pp[1] = rna_tf32_u(p1);
                }
                rs += __shfl_xor_sync(0xffffffffu, rs, 1);
                rs += __shfl_xor_sync(0xffffffffu, rs, 2);
                l_[tm][hh] += rs;
            }
        __syncwarp();

#pragma unroll
        for (int k8 = 0; k8 < 8; k8++) {
            uint32_t afrP[2][4];
#pragma unroll
            for (int tm = 0; tm < 2; tm++)
                ldsm4(pw + (tm * 16 + a_sub) * 272 + k8 * 32 + a_cb, afrP[tm]);
            uint32_t bfrV[4][2];
#pragma unroll
            for (int p = 0; p < 2; p++) {
                uint32_t r[4];
                ldsm4(sb + AT_VT + (p * 16 + b_sub) * 1040 + ch * 256 + k8 * 32 + b_cb, r);
                bfrV[2 * p][0] = r[0]; bfrV[2 * p][1] = r[1];
                bfrV[2 * p + 1][0] = r[2]; bfrV[2 * p + 1][1] = r[3];
            }
#pragma unroll
            for (int tm = 0; tm < 2; tm++)
#pragma unroll
                for (int jn = 0; jn < 4; jn++)
                    mma8(accpv[tm][jn], afrP[tm], bfrV[jn]);
        }
        __syncwarp();
    }

#pragma unroll
    for (int tm = 0; tm < 2; tm++)
#pragma unroll
        for (int hh = 0; hh < 2; hh++) {
            const float inv = 1.f / l_[tm][hh];
            const long row = base + wid * 32 + r4 + tm * 16 + hh * 8;
            float* op = out + row * E_DIM + hoff + c2;
#pragma unroll
            for (int jn = 0; jn < 4; jn++) {
                float2 o;
                o.x = rna_tf32(accpv[tm][jn][2 * hh + 0] * inv);
                o.y = rna_tf32(accpv[tm][jn][2 * hh + 1] * inv);
                *(float2*)(op + jn * 8) = o;
            }
        }
}

// ---------------------------------------------------------------------------
// LayerNorm: warp-per-row, 8 rows/CTA, float4 vectorized
// ---------------------------------------------------------------------------
template<bool DUAL>
__global__ __launch_bounds__(256) void layernorm_kernel(
    const float* __restrict__ in, const float* __restrict__ g,
    const float* __restrict__ b, float* __restrict__ out,
    float* __restrict__ out_r)
{
    const int wid = threadIdx.x >> 5;
    const int lane = threadIdx.x & 31;
    const long row = (long)blockIdx.x * 8 + wid;
    const float4* ip = (const float4*)(in + row * E_DIM);
    const float4 v0 = ip[lane * 2];
    const float4 v1 = ip[lane * 2 + 1];

    float s  = v0.x + v0.y + v0.z + v0.w + v1.x + v1.y + v1.z + v1.w;
    float sq = v0.x * v0.x + v0.y * v0.y + v0.z * v0.z + v0.w * v0.w
             + v1.x * v1.x + v1.y * v1.y + v1.z * v1.z + v1.w * v1.w;
#pragma unroll
    for (int o = 16; o; o >>= 1) {
        s  += __shfl_xor_sync(0xffffffffu, s,  o);
        sq += __shfl_xor_sync(0xffffffffu, sq, o);
    }
    const float mean = s * (1.f / E_DIM);
    const float var  = sq * (1.f / E_DIM) - mean * mean;
    const float r    = rsqrtf(var + LN_EPS);

    const float4 g0 = ((const float4*)g)[lane * 2];
    const float4 g1 = ((const float4*)g)[lane * 2 + 1];
    const float4 b0 = ((const float4*)b)[lane * 2];
    const float4 b1 = ((const float4*)b)[lane * 2 + 1];

    float4 o0, o1;
    o0.x = (v0.x - mean) * r * g0.x + b0.x;
    o0.y = (v0.y - mean) * r * g0.y + b0.y;
    o0.z = (v0.z - mean) * r * g0.z + b0.z;
    o0.w = (v0.w - mean) * r * g0.w + b0.w;
    o1.x = (v1.x - mean) * r * g1.x + b1.x;
    o1.y = (v1.y - mean) * r * g1.y + b1.y;
    o1.z = (v1.z - mean) * r * g1.z + b1.z;
    o1.w = (v1.w - mean) * r * g1.w + b1.w;

    float4* op = (float4*)(out + row * E_DIM);
    op[lane * 2] = o0;
    op[lane * 2 + 1] = o1;
    if (DUAL) {
        float4 r0, r1;
        r0.x = rna_tf32(o0.x); r0.y = rna_tf32(o0.y);
        r0.z = rna_tf32(o0.z); r0.w = rna_tf32(o0.w);
        r1.x = rna_tf32(o1.x); r1.y = rna_tf32(o1.y);
        r1.z = rna_tf32(o1.z); r1.w = rna_tf32(o1.w);
        float4* orp = (float4*)(out_r + row * E_DIM);
        orp[lane * 2] = r0;
        orp[lane * 2 + 1] = r1;
    }
}

// ---------------------------------------------------------------------------
extern "C" void kernel_launch(void* const* d_in, const int* in_sizes, int n_in,
                              void* d_out, int out_size)
{
    const float* x     = (const float*)d_in[0];
    const float* mask  = (const float*)d_in[1];
    const float* Wq    = (const float*)d_in[2];
    const float* Wk    = (const float*)d_in[3];
    const float* Wv    = (const float*)d_in[4];
    const float* Wo    = (const float*)d_in[5];
    const float* bo    = (const float*)d_in[6];
    const float* W1    = (const float*)d_in[7];
    const float* bf1   = (const float*)d_in[8];
    const float* W2    = (const float*)d_in[9];
    const float* bf2   = (const float*)d_in[10];
    const float* g1    = (const float*)d_in[11];
    const float* beta1 = (const float*)d_in[12];
    const float* g2    = (const float*)d_in[13];
    const float* beta2 = (const float*)d_in[14];
    float* out = (float*)d_out;

    float *xr, *qkv, *attn, *y1, *h1, *h1r, *hid, *y2;
    float *WqkvT, *WoT, *W1T, *W2T;
    cudaGetSymbolAddress((void**)&xr,    g_xr);
    cudaGetSymbolAddress((void**)&qkv,   g_qkv);
    cudaGetSymbolAddress((void**)&attn,  g_attn);
    cudaGetSymbolAddress((void**)&y1,    g_y1);
    cudaGetSymbolAddress((void**)&h1,    g_h1);
    cudaGetSymbolAddress((void**)&h1r,   g_h1r);
    cudaGetSymbolAddress((void**)&hid,   g_hid);
    cudaGetSymbolAddress((void**)&y2,    g_y2);
    cudaGetSymbolAddress((void**)&WqkvT, g_WqkvT);
    cudaGetSymbolAddress((void**)&WoT,   g_WoT);
    cudaGetSymbolAddress((void**)&W1T,   g_W1T);
    cudaGetSymbolAddress((void**)&W2T,   g_W2T);

    cudaFuncSetAttribute(gemm_mma<false, false, false, true>,
                         cudaFuncAttributeMaxDynamicSharedMemorySize, GSMEM);
    cudaFuncSetAttribute(gemm_mma<true, false, true, false>,
                         cudaFuncAttributeMaxDynamicSharedMemorySize, GSMEM);
    cudaFuncSetAttribute(gemm_mma<true, true, false, true>,
                         cudaFuncAttributeMaxDynamicSharedMemorySize, GSMEM);
    cudaFuncSetAttribute(attn_tc,
                         cudaFuncAttributeMaxDynamicSharedMemorySize, AT_SMEM);

    const dim3 blk(256);
    const dim3 tblk(32, 8);

    // prep: round x, build fused [SCALING*Wq; Wk; Wv]^T and other transposes
    round4_kernel<<<(T_TOK * E_DIM / 4 + 255) / 256, blk>>>((const float4*)x, (float4*)xr,
                                                            T_TOK * E_DIM / 4);
    transpose_w_kernel<<<dim3(8, 8), tblk>>>(Wq, WqkvT,                    E_DIM, E_DIM, SCALING);
    transpose_w_kernel<<<dim3(8, 8), tblk>>>(Wk, WqkvT + E_DIM * E_DIM,    E_DIM, E_DIM, 1.f);
    transpose_w_kernel<<<dim3(8, 8), tblk>>>(Wv, WqkvT + 2 * E_DIM * E_DIM, E_DIM, E_DIM, 1.f);
    transpose_w_kernel<<<dim3(8, 8), tblk>>>(Wo, WoT, E_DIM, E_DIM, 1.f);
    transpose_w_kernel<<<dim3(8, 32), tblk>>>(W1, W1T, E_DIM, FF_DIM, 1.f);
    transpose_w_kernel<<<dim3(32, 8), tblk>>>(W2, W2T, FF_DIM, E_DIM, 1.f);

    const dim3 gQKV(3 * E_DIM / BN, T_TOK / BM);   // (6, 512)
    const dim3 gE(E_DIM / BN, T_TOK / BM);         // (2, 512)
    const dim3 gF(FF_DIM / BN, T_TOK / BM);        // (8, 512)

    // fused QKV (tf32-rounded outputs)
    gemm_mma<false, false, false, true><<<gQKV, blk, GSMEM>>>(xr, WqkvT, qkv,
                                                              3 * E_DIM, E_DIM, 1.f,
                                                              nullptr, nullptr);

    // attention (tensor cores)
    attn_tc<<<2048, blk, AT_SMEM>>>(qkv, mask, attn);

    // y1 = x + attn @ Wo + bo ; h1 = LN1(y1), h1r = round(h1)
    gemm_mma<true, false, true, false><<<gE, blk, GSMEM>>>(attn, WoT, y1, E_DIM, E_DIM, 1.f, bo, x);
    layernorm_kernel<true><<<T_TOK / 8, blk>>>(y1, g1, beta1, h1, h1r);

    // hid = round(relu(h1r @ W1 + bf1))
    gemm_mma<true, true, false, true><<<gF, blk, GSMEM>>>(h1r, W1T, hid, FF_DIM, E_DIM, 1.f, bf1, nullptr);

    // y2 = h1 + hid @ W2 + bf2 ; out = LN2(y2)
    gemm_mma<true, false, true, false><<<gE, blk, GSMEM>>>(hid, W2T, y2, E_DIM, FF_DIM, 1.f, bf2, h1);
    layernorm_kernel<false><<<T_TOK / 8, blk>>>(y2, g2, beta2, out, nullptr);
}

// round 7
// speedup vs baseline: 3.9082x; 1.0954x over previous
#include <cuda_runtime.h>
#include <cstdint>

// ---------------------------------------------------------------------------
// EncoderLayer: B=16, N1=4, N2=4, N=256, E=256, H=8, DK=32
// T = 65536, E = 256, FF = 1024
// GEMMs (BM=128, BN=256, warp 64x64) + flash attention on mma.sync tf32.
// LayerNorms fused into the Wo / W2 GEMM epilogues.
// ---------------------------------------------------------------------------

#define T_TOK  65536
#define E_DIM  256
#define FF_DIM 1024
#define N_SEQ  256
#define DK     32
#define SCALING 0.17677669529663687f
#define LN_EPS 1e-5f

// ---------------- scratch ---------------------------------------------------
__device__ float g_xr   [T_TOK * E_DIM];
__device__ float g_qkv  [T_TOK * 3 * E_DIM];
__device__ float g_attn [T_TOK * E_DIM];
__device__ float g_h1   [T_TOK * E_DIM];
__device__ float g_h1r  [T_TOK * E_DIM];
__device__ float g_hid  [T_TOK * FF_DIM];
__device__ float g_WqkvT[3 * E_DIM * E_DIM];
__device__ float g_WoT  [E_DIM * E_DIM];
__device__ float g_W1T  [FF_DIM * E_DIM];
__device__ float g_W2T  [E_DIM * FF_DIM];

// ---------------- helpers ---------------------------------------------------
__device__ __forceinline__ uint32_t s2u(const void* p) {
    uint32_t a;
    asm("{ .reg .u64 t; cvta.to.shared.u64 t, %1; cvt.u32.u64 %0, t; }" : "=r"(a) : "l"(p));
    return a;
}
__device__ __forceinline__ float rna_tf32(float x) {
    uint32_t u;
    asm("cvt.rna.tf32.f32 %0, %1;" : "=r"(u) : "f"(x));
    return __uint_as_float(u);
}
__device__ __forceinline__ uint32_t rna_tf32_u(float x) {
    uint32_t u;
    asm("cvt.rna.tf32.f32 %0, %1;" : "=r"(u) : "f"(x));
    return u;
}
#define SWZ(o)  ((o) ^ (((o) >> 3) & 0x70))   // 128B rows

__device__ __forceinline__ void cpa16(uint32_t s, const void* g) {
    asm volatile("cp.async.cg.shared.global [%0], [%1], 16;" :: "r"(s), "l"(g));
}
#define CP_COMMIT() asm volatile("cp.async.commit_group;" ::: "memory")

__device__ __forceinline__ void ldsm4(uint32_t addr, uint32_t* r) {
    asm volatile("ldmatrix.sync.aligned.m8n8.x4.shared.b16 {%0,%1,%2,%3}, [%4];"
                 : "=r"(r[0]), "=r"(r[1]), "=r"(r[2]), "=r"(r[3]) : "r"(addr));
}
__device__ __forceinline__ void mma8(float* c, const uint32_t* a, const uint32_t* b) {
    asm volatile("mma.sync.aligned.m16n8k8.row.col.f32.tf32.tf32.f32 "
                 "{%0,%1,%2,%3}, {%4,%5,%6,%7}, {%8,%9}, {%0,%1,%2,%3};"
                 : "+f"(c[0]), "+f"(c[1]), "+f"(c[2]), "+f"(c[3])
                 : "r"(a[0]), "r"(a[1]), "r"(a[2]), "r"(a[3]), "r"(b[0]), "r"(b[1]));
}

// ---------------------------------------------------------------------------
// GEMM: BM=128, BN=256, BK=32, 4 stages, 8 warps (2m x 4n), warp tile 64x64.
// Optional fused LayerNorm over the 256-wide output row (requires Nt == 256).
// ---------------------------------------------------------------------------
#define BM 128
#define BN 256
#define BK 32
#define STG 4
#define ASZ (BM * BK * 4)            // 16384
#define BSZ (BN * BK * 4)            // 32768
#define STGB (ASZ + BSZ)             // 49152
#define REDB (STG * STGB)            // reduction buffer offset (192K)
#define GSMEM (REDB + 128 * 4 * 8)   // + red[128][4] float2 = 196608+4096

template<bool BIAS, bool RELU, bool RES, bool ROUND, bool LN, bool DUAL>
__global__ __launch_bounds__(256, 1) void gemm_mma(
    const float* __restrict__ A, const float* __restrict__ BT,
    float* __restrict__ C, float* __restrict__ C2, int Nt, int Kt,
    const float* __restrict__ bias, const float* __restrict__ resid,
    const float* __restrict__ gamma, const float* __restrict__ beta)
{
    extern __shared__ char smem[];
    const uint32_t sb = s2u(smem);
    const int tid = threadIdx.x;
    const int lane = tid & 31;
    const int wid = tid >> 5;
    const int wm = wid & 1;          // 2 m-warps
    const int wn = wid >> 1;         // 4 n-warps

    const int m0 = blockIdx.y * BM;
    const int n0 = blockIdx.x * BN;
    const float* Ag = A + (size_t)m0 * Kt;
    const float* Bg = BT + (size_t)n0 * Kt;
    const int nC = Kt / BK;

    auto load_stage = [&](int s, int c) {
        const uint32_t ab = sb + s * STGB;
        const uint32_t bb = ab + ASZ;
        const float* Ac = Ag + c * BK;
        const float* Bc = Bg + c * BK;
#pragma unroll
        for (int i = 0; i < 4; i++) {        // A: 128 rows x 8 granules
            int g = i * 256 + tid, r = g >> 3, cc = g & 7;
            cpa16(ab + SWZ(r * 128 + cc * 16), Ac + (size_t)r * Kt + cc * 4);
        }
#pragma unroll
        for (int i = 0; i < 8; i++) {        // B: 256 rows x 8 granules
            int g = i * 256 + tid, r = g >> 3, cc = g & 7;
            cpa16(bb + SWZ(r * 128 + cc * 16), Bc + (size_t)r * Kt + cc * 4);
        }
    };

    load_stage(0, 0); CP_COMMIT();
    load_stage(1, 1); CP_COMMIT();
    load_stage(2, 2); CP_COMMIT();

    float acc[4][8][4];
#pragma unroll
    for (int tm = 0; tm < 4; tm++)
#pragma unroll
        for (int j = 0; j < 8; j++)
#pragma unroll
            for (int e = 0; e < 4; e++) acc[tm][j][e] = 0.f;

    const int a_row = wm * 64 + (lane & 15);
    const int a_cb  = (lane >> 4) * 16;
    const int b_row = wn * 64 + (lane & 7) + ((lane >> 4) << 3);
    const int b_cb  = ((lane >> 3) & 1) * 16;

    for (int c = 0; c < nC; c++) {
        const int s = c & 3;
        asm volatile("cp.async.wait_group 2;" ::: "memory");
        __syncthreads();
        const uint32_t ab = sb + s * STGB;
        const uint32_t bb = ab + ASZ;
#pragma unroll
        for (int k8 = 0; k8 < 4; k8++) {
            uint32_t afr[4][4], bfr[8][2];
#pragma unroll
            for (int tm = 0; tm < 4; tm++)
                ldsm4(ab + SWZ((a_row + tm * 16) * 128 + k8 * 32 + a_cb), afr[tm]);
#pragma unroll
            for (int p = 0; p < 4; p++) {
                uint32_t r[4];
                ldsm4(bb + SWZ((b_row + p * 16) * 128 + k8 * 32 + b_cb), r);
                bfr[2 * p][0] = r[0]; bfr[2 * p][1] = r[1];
                bfr[2 * p + 1][0] = r[2]; bfr[2 * p + 1][1] = r[3];
            }
#pragma unroll
            for (int tm = 0; tm < 4; tm++)
#pragma unroll
                for (int j = 0; j < 8; j++)
                    mma8(acc[tm][j], afr[tm], bfr[j]);
        }
        __syncthreads();
        const int cn = c + 3;
        if (cn < nC) load_stage(cn & 3, cn);
        CP_COMMIT();
    }

    const int r4 = lane >> 2;
    const int c2 = (lane & 3) * 2;

    // ---- apply bias / residual (in place) ----
#pragma unroll
    for (int tm = 0; tm < 4; tm++) {
#pragma unroll
        for (int j = 0; j < 8; j++) {
            const int gc = n0 + wn * 64 + j * 8 + c2;
#pragma unroll
            for (int h = 0; h < 2; h++) {
                float v0 = acc[tm][j][2 * h + 0];
                float v1 = acc[tm][j][2 * h + 1];
                if (BIAS) {
                    const float2 bb = *(const float2*)(bias + gc);
                    v0 += bb.x; v1 += bb.y;
                }
                if (RES) {
                    const int gr = m0 + wm * 64 + tm * 16 + h * 8 + r4;
                    const float2 rr = *(const float2*)(resid + (size_t)gr * Nt + gc);
                    v0 += rr.x; v1 += rr.y;
                }
                if (RELU) { v0 = fmaxf(v0, 0.f); v1 = fmaxf(v1, 0.f); }
                acc[tm][j][2 * h + 0] = v0;
                acc[tm][j][2 * h + 1] = v1;
            }
        }
    }

    if (LN) {
        // cross-warp LayerNorm over 256 cols (Nt == 256, n0 == 0)
        float2* red = (float2*)(smem + REDB);
        __syncthreads();
#pragma unroll
        for (int tm = 0; tm < 4; tm++)
#pragma unroll
            for (int h = 0; h < 2; h++) {
                float s = 0.f, sq = 0.f;
#pragma unroll
                for (int j = 0; j < 8; j++) {
                    const float v0 = acc[tm][j][2 * h + 0];
                    const float v1 = acc[tm][j][2 * h + 1];
                    s += v0 + v1;
                    sq += v0 * v0 + v1 * v1;
                }
                s  += __shfl_xor_sync(0xffffffffu, s, 1);
                sq += __shfl_xor_sync(0xffffffffu, sq, 1);
                s  += __shfl_xor_sync(0xffffffffu, s, 2);
                sq += __shfl_xor_sync(0xffffffffu, sq, 2);
                if ((lane & 3) == 0) {
                    const int rl = wm * 64 + tm * 16 + h * 8 + r4;
                    red[rl * 4 + wn] = make_float2(s, sq);
                }
            }
        __syncthreads();

#pragma unroll
        for (int tm = 0; tm < 4; tm++)
#pragma unroll
            for (int h = 0; h < 2; h++) {
                const int rl = wm * 64 + tm * 16 + h * 8 + r4;
                float S = 0.f, SQ = 0.f;
#pragma unroll
                for (int i = 0; i < 4; i++) {
                    const float2 p = red[rl * 4 + i];
                    S += p.x; SQ += p.y;
                }
                const float mean = S * (1.f / 256.f);
                const float var  = SQ * (1.f / 256.f) - mean * mean;
                const float rr   = rsqrtf(var + LN_EPS);
                const size_t crow = (size_t)(m0 + rl) * 256;
#pragma unroll
                for (int j = 0; j < 8; j++) {
                    const int gc = wn * 64 + j * 8 + c2;
                    const float2 gg = *(const float2*)(gamma + gc);
                    const float2 bb = *(const float2*)(beta + gc);
                    float o0 = (acc[tm][j][2 * h + 0] - mean) * rr * gg.x + bb.x;
                    float o1 = (acc[tm][j][2 * h + 1] - mean) * rr * gg.y + bb.y;
                    *(float2*)(C + crow + gc) = make_float2(o0, o1);
                    if (DUAL)
                        *(float2*)(C2 + crow + gc) =
                            make_float2(rna_tf32(o0), rna_tf32(o1));
                }
            }
    } else {
#pragma unroll
        for (int tm = 0; tm < 4; tm++) {
#pragma unroll
            for (int j = 0; j < 8; j++) {
                const int gc = n0 + wn * 64 + j * 8 + c2;
#pragma unroll
                for (int h = 0; h < 2; h++) {
                    const int gr = m0 + wm * 64 + tm * 16 + h * 8 + r4;
                    float v0 = acc[tm][j][2 * h + 0];
                    float v1 = acc[tm][j][2 * h + 1];
                    if (ROUND) { v0 = rna_tf32(v0); v1 = rna_tf32(v1); }
                    *(float2*)(C + (size_t)gr * Nt + gc) = make_float2(v0, v1);
                }
            }
        }
    }
}

// ---------------------------------------------------------------------------
// Prep kernels
// ---------------------------------------------------------------------------
__global__ void round4_kernel(const float4* __restrict__ in, float4* __restrict__ out, int n4) {
    int i = blockIdx.x * blockDim.x + threadIdx.x;
    if (i < n4) {
        float4 v = in[i];
        v.x = rna_tf32(v.x); v.y = rna_tf32(v.y); v.z = rna_tf32(v.z); v.w = rna_tf32(v.w);
        out[i] = v;
    }
}
__global__ void transpose_w_kernel(const float* __restrict__ W, float* __restrict__ WT,
                                   int K, int N, float scale) {
    __shared__ float t[32][33];
    const int kb = blockIdx.x * 32, nb = blockIdx.y * 32;
    const int tx = threadIdx.x, ty = threadIdx.y;
    for (int i = ty; i < 32; i += 8)
        t[i][tx] = W[(size_t)(kb + i) * N + nb + tx];
    __syncthreads();
    for (int i = ty; i < 32; i += 8)
        WT[(size_t)(nb + i) * K + kb + tx] = rna_tf32(t[tx][i] * scale);
}

// ---------------------------------------------------------------------------
// Tensor-core flash attention (proven in rounds 4-5).
// ---------------------------------------------------------------------------
#define QKV_LD (3 * E_DIM)
#define AT_Q   0
#define AT_K   32768
#define AT_VT  65536
#define AT_P   98816
#define AT_SMEM (AT_P + 8 * 8704)

__global__ __launch_bounds__(256, 1) void attn_tc(
    const float* __restrict__ qkv, const float* __restrict__ mask,
    float* __restrict__ out)
{
    extern __shared__ char smem[];
    const uint32_t sb = s2u(smem);
    float* smf = (float*)smem;

    const int bx = blockIdx.x;
    const int g  = bx >> 3;
    const int h  = bx & 7;
    const long base = (long)g * N_SEQ;
    const int hoff = h * DK;
    const int n12 = g & 15;
    const int tid = threadIdx.x;
    const int lane = tid & 31;
    const int wid = tid >> 5;

#pragma unroll
    for (int t = 0; t < 8; t++) {
        const int idx = t * 256 + tid;
        const int row = idx >> 3, cg = idx & 7;
        const long src = (base + row) * QKV_LD + hoff + cg * 4;
        cpa16(sb + AT_Q + SWZ(row * 128 + cg * 16), qkv + src);
        cpa16(sb + AT_K + SWZ(row * 128 + cg * 16), qkv + src + E_DIM);
        cpa16(sb + AT_P + SWZ(row * 128 + cg * 16), qkv + src + 2 * E_DIM);
    }
    CP_COMMIT();
    asm volatile("cp.async.wait_group 0;" ::: "memory");
    __syncthreads();

#pragma unroll
    for (int t = 0; t < 8; t++) {
        const int idx = t * 256 + tid;
        const int key = idx >> 3, dg = idx & 7;
        float4 vv = *(const float4*)(smem + AT_P + SWZ(key * 128 + dg * 16));
        float* vt = smf + AT_VT / 4;
        vt[(dg * 4 + 0) * 260 + key] = vv.x;
        vt[(dg * 4 + 1) * 260 + key] = vv.y;
        vt[(dg * 4 + 2) * 260 + key] = vv.z;
        vt[(dg * 4 + 3) * 260 + key] = vv.w;
    }
    __syncthreads();

    const int a_sub = lane & 15;
    const int a_cb  = (lane >> 4) * 16;
    uint32_t qfr[2][4][4];
#pragma unroll
    for (int tm = 0; tm < 2; tm++)
#pragma unroll
        for (int k8 = 0; k8 < 4; k8++)
            ldsm4(sb + AT_Q + SWZ((wid * 32 + tm * 16 + a_sub) * 128 + k8 * 32 + a_cb),
                  qfr[tm][k8]);

    const int b_sub = (lane & 7) + ((lane >> 4) << 3);
    const int b_cb  = ((lane >> 3) & 1) * 16;

    float m_[2][2], l_[2][2], accpv[2][4][4];
#pragma unroll
    for (int tm = 0; tm < 2; tm++)
#pragma unroll
        for (int hh = 0; hh < 2; hh++) { m_[tm][hh] = -1e30f; l_[tm][hh] = 0.f; }
#pragma unroll
    for (int tm = 0; tm < 2; tm++)
#pragma unroll
        for (int jn = 0; jn < 4; jn++)
#pragma unroll
            for (int e = 0; e < 4; e++) accpv[tm][jn][e] = 0.f;

    const uint32_t pw = sb + AT_P + wid * 8704;
    const int r4 = lane >> 2;
    const int c2 = (lane & 3) * 2;

    for (int ch = 0; ch < 4; ch++) {
        float accS[2][8][4];
#pragma unroll
        for (int tm = 0; tm < 2; tm++)
#pragma unroll
            for (int j = 0; j < 8; j++)
#pragma unroll
                for (int e = 0; e < 4; e++) accS[tm][j][e] = 0.f;

#pragma unroll
        for (int k8 = 0; k8 < 4; k8++) {
            uint32_t bfr[8][2];
#pragma unroll
            for (int p = 0; p < 4; p++) {
                uint32_t r[4];
                ldsm4(sb + AT_K + SWZ((ch * 64 + p * 16 + b_sub) * 128 + k8 * 32 + b_cb), r);
                bfr[2 * p][0] = r[0]; bfr[2 * p][1] = r[1];
                bfr[2 * p + 1][0] = r[2]; bfr[2 * p + 1][1] = r[3];
            }
#pragma unroll
            for (int tm = 0; tm < 2; tm++)
#pragma unroll
                for (int j = 0; j < 8; j++)
                    mma8(accS[tm][j], qfr[tm][k8], bfr[j]);
        }

#pragma unroll
        for (int tm = 0; tm < 2; tm++)
#pragma unroll
            for (int hh = 0; hh < 2; hh++) {
                const int grow = wid * 32 + r4 + tm * 16 + hh * 8;
                const float* mp = mask + ((size_t)(n12 * N_SEQ + grow)) * N_SEQ + ch * 64 + c2;
#pragma unroll
                for (int j = 0; j < 8; j++) {
                    const float2 mm = *(const float2*)(mp + j * 8);
                    accS[tm][j][2 * hh + 0] += mm.x;
                    accS[tm][j][2 * hh + 1] += mm.y;
                }
            }

#pragma unroll
        for (int tm = 0; tm < 2; tm++)
#pragma unroll
            for (int hh = 0; hh < 2; hh++) {
                float mx = -1e30f;
#pragma unroll
                for (int j = 0; j < 8; j++) {
                    mx = fmaxf(mx, accS[tm][j][2 * hh + 0]);
                    mx = fmaxf(mx, accS[tm][j][2 * hh + 1]);
                }
                mx = fmaxf(mx, __shfl_xor_sync(0xffffffffu, mx, 1));
                mx = fmaxf(mx, __shfl_xor_sync(0xffffffffu, mx, 2));
                const float mnew = fmaxf(m_[tm][hh], mx);
                const float sc = __expf(m_[tm][hh] - mnew);
                m_[tm][hh] = mnew;
                l_[tm][hh] *= sc;
#pragma unroll
                for (int jn = 0; jn < 4; jn++) {
                    accpv[tm][jn][2 * hh + 0] *= sc;
                    accpv[tm][jn][2 * hh + 1] *= sc;
                }
                float rs = 0.f;
#pragma unroll
                for (int j = 0; j < 8; j++) {
                    const float p0 = __expf(accS[tm][j][2 * hh + 0] - mnew);
                    const float p1 = __expf(accS[tm][j][2 * hh + 1] - mnew);
                    rs += p0 + p1;
                    const int prow = r4 + tm * 16 + hh * 8;
                    uint32_t* pp = (uint32_t*)(smem + (pw - sb)) + prow * 68 + c2 + j * 8;
                    pp[0] = rna_tf32_u(p0);
                    pp[1] = rna_tf32_u(p1);
                }
                rs += __shfl_xor_sync(0xffffffffu, rs, 1);
                rs += __shfl_xor_sync(0xffffffffu, rs, 2);
                l_[tm][hh] += rs;
            }
        __syncwarp();

#pragma unroll
        for (int k8 = 0; k8 < 8; k8++) {
            uint32_t afrP[2][4];
#pragma unroll
            for (int tm = 0; tm < 2; tm++)
                ldsm4(pw + (tm * 16 + a_sub) * 272 + k8 * 32 + a_cb, afrP[tm]);
            uint32_t bfrV[4][2];
#pragma unroll
            for (int p = 0; p < 2; p++) {
                uint32_t r[4];
                ldsm4(sb + AT_VT + (p * 16 + b_sub) * 1040 + ch * 256 + k8 * 32 + b_cb, r);
                bfrV[2 * p][0] = r[0]; bfrV[2 * p][1] = r[1];
                bfrV[2 * p + 1][0] = r[2]; bfrV[2 * p + 1][1] = r[3];
            }
#pragma unroll
            for (int tm = 0; tm < 2; tm++)
#pragma unroll
                for (int jn = 0; jn < 4; jn++)
                    mma8(accpv[tm][jn], afrP[tm], bfrV[jn]);
        }
        __syncwarp();
    }

#pragma unroll
    for (int tm = 0; tm < 2; tm++)
#pragma unroll
        for (int hh = 0; hh < 2; hh++) {
            const float inv = 1.f / l_[tm][hh];
            const long row = base + wid * 32 + r4 + tm * 16 + hh * 8;
            float* op = out + row * E_DIM + hoff + c2;
#pragma unroll
            for (int jn = 0; jn < 4; jn++) {
                float2 o;
                o.x = rna_tf32(accpv[tm][jn][2 * hh + 0] * inv);
                o.y = rna_tf32(accpv[tm][jn][2 * hh + 1] * inv);
                *(float2*)(op + jn * 8) = o;
            }
        }
}

// ---------------------------------------------------------------------------
extern "C" void kernel_launch(void* const* d_in, const int* in_sizes, int n_in,
                              void* d_out, int out_size)
{
    const float* x     = (const float*)d_in[0];
    const float* mask  = (const float*)d_in[1];
    const float* Wq    = (const float*)d_in[2];
    const float* Wk    = (const float*)d_in[3];
    const float* Wv    = (const float*)d_in[4];
    const float* Wo    = (const float*)d_in[5];
    const float* bo    = (const float*)d_in[6];
    const float* W1    = (const float*)d_in[7];
    const float* bf1   = (const float*)d_in[8];
    const float* W2    = (const float*)d_in[9];
    const float* bf2   = (const float*)d_in[10];
    const float* g1    = (const float*)d_in[11];
    const float* beta1 = (const float*)d_in[12];
    const float* g2    = (const float*)d_in[13];
    const float* beta2 = (const float*)d_in[14];
    float* out = (float*)d_out;

    float *xr, *qkv, *attn, *h1, *h1r, *hid;
    float *WqkvT, *WoT, *W1T, *W2T;
    cudaGetSymbolAddress((void**)&xr,    g_xr);
    cudaGetSymbolAddress((void**)&qkv,   g_qkv);
    cudaGetSymbolAddress((void**)&attn,  g_attn);
    cudaGetSymbolAddress((void**)&h1,    g_h1);
    cudaGetSymbolAddress((void**)&h1r,   g_h1r);
    cudaGetSymbolAddress((void**)&hid,   g_hid);
    cudaGetSymbolAddress((void**)&WqkvT, g_WqkvT);
    cudaGetSymbolAddress((void**)&WoT,   g_WoT);
    cudaGetSymbolAddress((void**)&W1T,   g_W1T);
    cudaGetSymbolAddress((void**)&W2T,   g_W2T);

    // instantiations
    auto k_qkv = gemm_mma<false, false, false, true,  false, false>;
    auto k_ff1 = gemm_mma<true,  true,  false, true,  false, false>;
    auto k_ln1 = gemm_mma<true,  false, true,  false, true,  true >;
    auto k_ln2 = gemm_mma<true,  false, true,  false, true,  false>;

    cudaFuncSetAttribute(k_qkv, cudaFuncAttributeMaxDynamicSharedMemorySize, GSMEM);
    cudaFuncSetAttribute(k_ff1, cudaFuncAttributeMaxDynamicSharedMemorySize, GSMEM);
    cudaFuncSetAttribute(k_ln1, cudaFuncAttributeMaxDynamicSharedMemorySize, GSMEM);
    cudaFuncSetAttribute(k_ln2, cudaFuncAttributeMaxDynamicSharedMemorySize, GSMEM);
    cudaFuncSetAttribute(attn_tc, cudaFuncAttributeMaxDynamicSharedMemorySize, AT_SMEM);

    const dim3 blk(256);
    const dim3 tblk(32, 8);

    // prep
    round4_kernel<<<(T_TOK * E_DIM / 4 + 255) / 256, blk>>>((const float4*)x, (float4*)xr,
                                                            T_TOK * E_DIM / 4);
    transpose_w_kernel<<<dim3(8, 8), tblk>>>(Wq, WqkvT,                     E_DIM, E_DIM, SCALING);
    transpose_w_kernel<<<dim3(8, 8), tblk>>>(Wk, WqkvT + E_DIM * E_DIM,     E_DIM, E_DIM, 1.f);
    transpose_w_kernel<<<dim3(8, 8), tblk>>>(Wv, WqkvT + 2 * E_DIM * E_DIM, E_DIM, E_DIM, 1.f);
    transpose_w_kernel<<<dim3(8, 8), tblk>>>(Wo, WoT, E_DIM, E_DIM, 1.f);
    transpose_w_kernel<<<dim3(8, 32), tblk>>>(W1, W1T, E_DIM, FF_DIM, 1.f);
    transpose_w_kernel<<<dim3(32, 8), tblk>>>(W2, W2T, FF_DIM, E_DIM, 1.f);

    const dim3 gQKV(3, T_TOK / BM);   // Nt = 768
    const dim3 gE(1, T_TOK / BM);     // Nt = 256
    const dim3 gF(4, T_TOK / BM);     // Nt = 1024

    // fused QKV -> qkv[T,768] (rounded)
    k_qkv<<<gQKV, blk, GSMEM>>>(xr, WqkvT, qkv, nullptr, 3 * E_DIM, E_DIM,
                                nullptr, nullptr, nullptr, nullptr);

    // attention
    attn_tc<<<2048, blk, AT_SMEM>>>(qkv, mask, attn);

    // h1 = LN1(x + attn @ Wo + bo), h1r = round(h1)  [fused epilogue]
    k_ln1<<<gE, blk, GSMEM>>>(attn, WoT, h1, h1r, E_DIM, E_DIM,
                              bo, x, g1, beta1);

    // hid = round(relu(h1r @ W1 + bf1))
    k_ff1<<<gF, blk, GSMEM>>>(h1r, W1T, hid, nullptr, FF_DIM, E_DIM,
                              bf1, nullptr, nullptr, nullptr);

    // out = LN2(h1 + hid @ W2 + bf2)  [fused epilogue]
    k_ln2<<<gE, blk, GSMEM>>>(hid, W2T, out, nullptr, E_DIM, FF_DIM,
                              bf2, h1, g2, beta2);
}

// round 8
// speedup vs baseline: 4.0712x; 1.0417x over previous
#include <cuda_runtime.h>
#include <cstdint>

// ---------------------------------------------------------------------------
// EncoderLayer: B=16, N1=4, N2=4, N=256, E=256, H=8, DK=32
// T = 65536, E = 256, FF = 1024
// GEMMs (BM=128, BN=256, 512 thr, warp 32x64) + flash attention, mma.sync tf32.
// LayerNorms fused into Wo / W2 GEMM epilogues. One fused prep kernel.
// ---------------------------------------------------------------------------

#define T_TOK  65536
#define E_DIM  256
#define FF_DIM 1024
#define N_SEQ  256
#define DK     32
#define SCALING 0.17677669529663687f
#define LN_EPS 1e-5f

// ---------------- scratch ---------------------------------------------------
__device__ float g_xr   [T_TOK * E_DIM];
__device__ float g_qkv  [T_TOK * 3 * E_DIM];
__device__ float g_attn [T_TOK * E_DIM];
__device__ float g_h1   [T_TOK * E_DIM];
__device__ float g_h1r  [T_TOK * E_DIM];
__device__ float g_hid  [T_TOK * FF_DIM];
__device__ float g_WqkvT[3 * E_DIM * E_DIM];
__device__ float g_WoT  [E_DIM * E_DIM];
__device__ float g_W1T  [FF_DIM * E_DIM];
__device__ float g_W2T  [E_DIM * FF_DIM];

// ---------------- helpers ---------------------------------------------------
__device__ __forceinline__ uint32_t s2u(const void* p) {
    uint32_t a;
    asm("{ .reg .u64 t; cvta.to.shared.u64 t, %1; cvt.u32.u64 %0, t; }" : "=r"(a) : "l"(p));
    return a;
}
__device__ __forceinline__ float rna_tf32(float x) {
    uint32_t u;
    asm("cvt.rna.tf32.f32 %0, %1;" : "=r"(u) : "f"(x));
    return __uint_as_float(u);
}
__device__ __forceinline__ uint32_t rna_tf32_u(float x) {
    uint32_t u;
    asm("cvt.rna.tf32.f32 %0, %1;" : "=r"(u) : "f"(x));
    return u;
}
#define SWZ(o)  ((o) ^ (((o) >> 3) & 0x70))   // 128B rows

__device__ __forceinline__ void cpa16(uint32_t s, const void* g) {
    asm volatile("cp.async.cg.shared.global [%0], [%1], 16;" :: "r"(s), "l"(g));
}
#define CP_COMMIT() asm volatile("cp.async.commit_group;" ::: "memory")

__device__ __forceinline__ void ldsm4(uint32_t addr, uint32_t* r) {
    asm volatile("ldmatrix.sync.aligned.m8n8.x4.shared.b16 {%0,%1,%2,%3}, [%4];"
                 : "=r"(r[0]), "=r"(r[1]), "=r"(r[2]), "=r"(r[3]) : "r"(addr));
}
__device__ __forceinline__ void mma8(float* c, const uint32_t* a, const uint32_t* b) {
    asm volatile("mma.sync.aligned.m16n8k8.row.col.f32.tf32.tf32.f32 "
                 "{%0,%1,%2,%3}, {%4,%5,%6,%7}, {%8,%9}, {%0,%1,%2,%3};"
                 : "+f"(c[0]), "+f"(c[1]), "+f"(c[2]), "+f"(c[3])
                 : "r"(a[0]), "r"(a[1]), "r"(a[2]), "r"(a[3]), "r"(b[0]), "r"(b[1]));
}

// ---------------------------------------------------------------------------
// GEMM: BM=128, BN=256, BK=32, 4 stages, 512 threads (16 warps, 4m x 4n),
// warp tile 32x64. Optional fused LayerNorm over 256-wide rows (Nt == 256).
// ---------------------------------------------------------------------------
#define BM 128
#define BN 256
#define BK 32
#define STG 4
#define ASZ (BM * BK * 4)            // 16384
#define BSZ (BN * BK * 4)            // 32768
#define STGB (ASZ + BSZ)             // 49152
#define REDB (STG * STGB)            // 196608
#define GSMEM (REDB + 128 * 4 * 8)   // + red[128][4] float2

template<bool BIAS, bool RELU, bool RES, bool ROUND, bool LN, bool DUAL>
__global__ __launch_bounds__(512, 1) void gemm_mma(
    const float* __restrict__ A, const float* __restrict__ BT,
    float* __restrict__ C, float* __restrict__ C2, int Nt, int Kt,
    const float* __restrict__ bias, const float* __restrict__ resid,
    const float* __restrict__ gamma, const float* __restrict__ beta)
{
    extern __shared__ char smem[];
    const uint32_t sb = s2u(smem);
    const int tid = threadIdx.x;
    const int lane = tid & 31;
    const int wid = tid >> 5;
    const int wm = wid & 3;          // 4 m-warps (32 rows each)
    const int wn = wid >> 2;         // 4 n-warps (64 cols each)

    const int m0 = blockIdx.y * BM;
    const int n0 = blockIdx.x * BN;
    const float* Ag = A + (size_t)m0 * Kt;
    const float* Bg = BT + (size_t)n0 * Kt;
    const int nC = Kt / BK;

    auto load_stage = [&](int s, int c) {
        const uint32_t ab = sb + s * STGB;
        const uint32_t bb = ab + ASZ;
        const float* Ac = Ag + c * BK;
        const float* Bc = Bg + c * BK;
#pragma unroll
        for (int i = 0; i < 2; i++) {        // A: 128 rows x 8 granules = 1024
            int g = i * 512 + tid, r = g >> 3, cc = g & 7;
            cpa16(ab + SWZ(r * 128 + cc * 16), Ac + (size_t)r * Kt + cc * 4);
        }
#pragma unroll
        for (int i = 0; i < 4; i++) {        // B: 256 rows x 8 granules = 2048
            int g = i * 512 + tid, r = g >> 3, cc = g & 7;
            cpa16(bb + SWZ(r * 128 + cc * 16), Bc + (size_t)r * Kt + cc * 4);
        }
    };

    load_stage(0, 0); CP_COMMIT();
    load_stage(1, 1); CP_COMMIT();
    load_stage(2, 2); CP_COMMIT();

    float acc[2][8][4];
#pragma unroll
    for (int tm = 0; tm < 2; tm++)
#pragma unroll
        for (int j = 0; j < 8; j++)
#pragma unroll
            for (int e = 0; e < 4; e++) acc[tm][j][e] = 0.f;

    const int a_row = wm * 32 + (lane & 15);
    const int a_cb  = (lane >> 4) * 16;
    const int b_row = wn * 64 + (lane & 7) + ((lane >> 4) << 3);
    const int b_cb  = ((lane >> 3) & 1) * 16;

    for (int c = 0; c < nC; c++) {
        const int s = c & 3;
        asm volatile("cp.async.wait_group 2;" ::: "memory");
        __syncthreads();
        // issue next stage load BEFORE compute (stage (c+3)&3 was freed last iter)
        const int cn = c + 3;
        if (cn < nC) load_stage(cn & 3, cn);
        CP_COMMIT();

        const uint32_t ab = sb + s * STGB;
        const uint32_t bb = ab + ASZ;
#pragma unroll
        for (int k8 = 0; k8 < 4; k8++) {
            uint32_t afr[2][4], bfr[8][2];
#pragma unroll
            for (int tm = 0; tm < 2; tm++)
                ldsm4(ab + SWZ((a_row + tm * 16) * 128 + k8 * 32 + a_cb), afr[tm]);
#pragma unroll
            for (int p = 0; p < 4; p++) {
                uint32_t r[4];
                ldsm4(bb + SWZ((b_row + p * 16) * 128 + k8 * 32 + b_cb), r);
                bfr[2 * p][0] = r[0]; bfr[2 * p][1] = r[1];
                bfr[2 * p + 1][0] = r[2]; bfr[2 * p + 1][1] = r[3];
            }
#pragma unroll
            for (int tm = 0; tm < 2; tm++)
#pragma unroll
                for (int j = 0; j < 8; j++)
                    mma8(acc[tm][j], afr[tm], bfr[j]);
        }
        __syncthreads();
    }

    const int r4 = lane >> 2;
    const int c2 = (lane & 3) * 2;

    // ---- bias / residual / relu (in place) ----
#pragma unroll
    for (int tm = 0; tm < 2; tm++) {
#pragma unroll
        for (int j = 0; j < 8; j++) {
            const int gc = n0 + wn * 64 + j * 8 + c2;
#pragma unroll
            for (int h = 0; h < 2; h++) {
                float v0 = acc[tm][j][2 * h + 0];
                float v1 = acc[tm][j][2 * h + 1];
                if (BIAS) {
                    const float2 bb = *(const float2*)(bias + gc);
                    v0 += bb.x; v1 += bb.y;
                }
                if (RES) {
                    const int gr = m0 + wm * 32 + tm * 16 + h * 8 + r4;
                    const float2 rr = *(const float2*)(resid + (size_t)gr * Nt + gc);
                    v0 += rr.x; v1 += rr.y;
                }
                if (RELU) { v0 = fmaxf(v0, 0.f); v1 = fmaxf(v1, 0.f); }
                acc[tm][j][2 * h + 0] = v0;
                acc[tm][j][2 * h + 1] = v1;
            }
        }
    }

    if (LN) {
        // cross-warp LayerNorm over 256 cols (Nt == 256, n0 == 0)
        float2* red = (float2*)(smem + REDB);
        __syncthreads();
#pragma unroll
        for (int tm = 0; tm < 2; tm++)
#pragma unroll
            for (int h = 0; h < 2; h++) {
                float s = 0.f, sq = 0.f;
#pragma unroll
                for (int j = 0; j < 8; j++) {
                    const float v0 = acc[tm][j][2 * h + 0];
                    const float v1 = acc[tm][j][2 * h + 1];
                    s += v0 + v1;
                    sq += v0 * v0 + v1 * v1;
                }
                s  += __shfl_xor_sync(0xffffffffu, s, 1);
                sq += __shfl_xor_sync(0xffffffffu, sq, 1);
                s  += __shfl_xor_sync(0xffffffffu, s, 2);
                sq += __shfl_xor_sync(0xffffffffu, sq, 2);
                if ((lane & 3) == 0) {
                    const int rl = wm * 32 + tm * 16 + h * 8 + r4;
                    red[rl * 4 + wn] = make_float2(s, sq);
                }
            }
        __syncthreads();

#pragma unroll
        for (int tm = 0; tm < 2; tm++)
#pragma unroll
            for (int h = 0; h < 2; h++) {
                const int rl = wm * 32 + tm * 16 + h * 8 + r4;
                float S = 0.f, SQ = 0.f;
#pragma unroll
                for (int i = 0; i < 4; i++) {
                    const float2 p = red[rl * 4 + i];
                    S += p.x; SQ += p.y;
                }
                const float mean = S * (1.f / 256.f);
                const float var  = SQ * (1.f / 256.f) - mean * mean;
                const float rr   = rsqrtf(var + LN_EPS);
                const size_t crow = (size_t)(m0 + rl) * 256;
#pragma unroll
                for (int j = 0; j < 8; j++) {
                    const int gc = wn * 64 + j * 8 + c2;
                    const float2 gg = *(const float2*)(gamma + gc);
                    const float2 bb = *(const float2*)(beta + gc);
                    float o0 = (acc[tm][j][2 * h + 0] - mean) * rr * gg.x + bb.x;
                    float o1 = (acc[tm][j][2 * h + 1] - mean) * rr * gg.y + bb.y;
                    *(float2*)(C + crow + gc) = make_float2(o0, o1);
                    if (DUAL)
                        *(float2*)(C2 + crow + gc) =
                            make_float2(rna_tf32(o0), rna_tf32(o1));
                }
            }
    } else {
#pragma unroll
        for (int tm = 0; tm < 2; tm++) {
#pragma unroll
            for (int j = 0; j < 8; j++) {
                const int gc = n0 + wn * 64 + j * 8 + c2;
#pragma unroll
                for (int h = 0; h < 2; h++) {
                    const int gr = m0 + wm * 32 + tm * 16 + h * 8 + r4;
                    float v0 = acc[tm][j][2 * h + 0];
                    float v1 = acc[tm][j][2 * h + 1];
                    if (ROUND) { v0 = rna_tf32(v0); v1 = rna_tf32(v1); }
                    *(float2*)(C + (size_t)gr * Nt + gc) = make_float2(v0, v1);
                }
            }
        }
    }
}

// ---------------------------------------------------------------------------
// Fused prep: blocks [0, NR_BLK) round x -> xr; remaining blocks transpose
// the 6 weight matrices (32x32 tiles) into [N,K] layouts with tf32 rounding.
// ---------------------------------------------------------------------------
#define NR_BLK 8192
#define N4_X   (T_TOK * E_DIM / 4)   // 4194304

__global__ __launch_bounds__(256) void prep_kernel(
    const float4* __restrict__ x4, float4* __restrict__ xr4,
    const float* __restrict__ Wq, const float* __restrict__ Wk,
    const float* __restrict__ Wv, const float* __restrict__ Wo,
    const float* __restrict__ W1, const float* __restrict__ W2,
    float* __restrict__ WqkvT, float* __restrict__ WoT,
    float* __restrict__ W1T, float* __restrict__ W2T)
{
    const int b = blockIdx.x;
    const int tid = threadIdx.x;

    if (b < NR_BLK) {
        int i = b * 256 + tid;
#pragma unroll
        for (int it = 0; it < 2; it++) {
            float4 v = x4[i];
            v.x = rna_tf32(v.x); v.y = rna_tf32(v.y);
            v.z = rna_tf32(v.z); v.w = rna_tf32(v.w);
            xr4[i] = v;
            i += NR_BLK * 256;
        }
        return;
    }

    // transpose work
    __shared__ float t[32][33];
    const int idx = b - NR_BLK;
    const float* W; float* WT; int K, N, kb, nb; float scale = 1.f;
    if (idx < 64) {            // Wq
        W = Wq; WT = WqkvT; K = 256; N = 256; scale = SCALING;
        kb = (idx & 7) * 32; nb = (idx >> 3) * 32;
    } else if (idx < 128) {    // Wk
        W = Wk; WT = WqkvT + 256 * 256; K = 256; N = 256;
        kb = ((idx - 64) & 7) * 32; nb = ((idx - 64) >> 3) * 32;
    } else if (idx < 192) {    // Wv
        W = Wv; WT = WqkvT + 2 * 256 * 256; K = 256; N = 256;
        kb = ((idx - 128) & 7) * 32; nb = ((idx - 128) >> 3) * 32;
    } else if (idx < 256) {    // Wo
        W = Wo; WT = WoT; K = 256; N = 256;
        kb = ((idx - 192) & 7) * 32; nb = ((idx - 192) >> 3) * 32;
    } else if (idx < 512) {    // W1: K=256, N=1024
        W = W1; WT = W1T; K = 256; N = 1024;
        kb = ((idx - 256) & 7) * 32; nb = ((idx - 256) >> 3) * 32;
    } else {                   // W2: K=1024, N=256
        W = W2; WT = W2T; K = 1024; N = 256;
        kb = ((idx - 512) & 31) * 32; nb = ((idx - 512) >> 5) * 32;
    }
    const int tx = tid & 31, ty = tid >> 5;
    for (int i = ty; i < 32; i += 8)
        t[i][tx] = W[(size_t)(kb + i) * N + nb + tx];
    __syncthreads();
    for (int i = ty; i < 32; i += 8)
        WT[(size_t)(nb + i) * K + kb + tx] = rna_tf32(t[tx][i] * scale);
}

// ---------------------------------------------------------------------------
// Tensor-core flash attention (proven rounds 4-7).
// ---------------------------------------------------------------------------
#define QKV_LD (3 * E_DIM)
#define AT_Q   0
#define AT_K   32768
#define AT_VT  65536
#define AT_P   98816
#define AT_SMEM (AT_P + 8 * 8704)

__global__ __launch_bounds__(256, 1) void attn_tc(
    const float* __restrict__ qkv, const float* __restrict__ mask,
    float* __restrict__ out)
{
    extern __shared__ char smem[];
    const uint32_t sb = s2u(smem);
    float* smf = (float*)smem;

    const int bx = blockIdx.x;
    const int g  = bx >> 3;
    const int h  = bx & 7;
    const long base = (long)g * N_SEQ;
    const int hoff = h * DK;
    const int n12 = g & 15;
    const int tid = threadIdx.x;
    const int lane = tid & 31;
    const int wid = tid >> 5;

#pragma unroll
    for (int t = 0; t < 8; t++) {
        const int idx = t * 256 + tid;
        const int row = idx >> 3, cg = idx & 7;
        const long src = (base + row) * QKV_LD + hoff + cg * 4;
        cpa16(sb + AT_Q + SWZ(row * 128 + cg * 16), qkv + src);
        cpa16(sb + AT_K + SWZ(row * 128 + cg * 16), qkv + src + E_DIM);
        cpa16(sb + AT_P + SWZ(row * 128 + cg * 16), qkv + src + 2 * E_DIM);
    }
    CP_COMMIT();
    asm volatile("cp.async.wait_group 0;" ::: "memory");
    __syncthreads();

#pragma unroll
    for (int t = 0; t < 8; t++) {
        const int idx = t * 256 + tid;
        const int key = idx >> 3, dg = idx & 7;
        float4 vv = *(const float4*)(smem + AT_P + SWZ(key * 128 + dg * 16));
        float* vt = smf + AT_VT / 4;
        vt[(dg * 4 + 0) * 260 + key] = vv.x;
        vt[(dg * 4 + 1) * 260 + key] = vv.y;
        vt[(dg * 4 + 2) * 260 + key] = vv.z;
        vt[(dg * 4 + 3) * 260 + key] = vv.w;
    }
    __syncthreads();

    const int a_sub = lane & 15;
    const int a_cb  = (lane >> 4) * 16;
    uint32_t qfr[2][4][4];
#pragma unroll
    for (int tm = 0; tm < 2; tm++)
#pragma unroll
        for (int k8 = 0; k8 < 4; k8++)
            ldsm4(sb + AT_Q + SWZ((wid * 32 + tm * 16 + a_sub) * 128 + k8 * 32 + a_cb),
                  qfr[tm][k8]);

    const int b_sub = (lane & 7) + ((lane >> 4) << 3);
    const int b_cb  = ((lane >> 3) & 1) * 16;

    float m_[2][2], l_[2][2], accpv[2][4][4];
#pragma unroll
    for (int tm = 0; tm < 2; tm++)
#pragma unroll
        for (int hh = 0; hh < 2; hh++) { m_[tm][hh] = -1e30f; l_[tm][hh] = 0.f; }
#pragma unroll
    for (int tm = 0; tm < 2; tm++)
#pragma unroll
        for (int jn = 0; jn < 4; jn++)
#pragma unroll
            for (int e = 0; e < 4; e++) accpv[tm][jn][e] = 0.f;

    const uint32_t pw = sb + AT_P + wid * 8704;
    const int r4 = lane >> 2;
    const int c2 = (lane & 3) * 2;

    for (int ch = 0; ch < 4; ch++) {
        float accS[2][8][4];
#pragma unroll
        for (int tm = 0; tm < 2; tm++)
#pragma unroll
            for (int j = 0; j < 8; j++)
#pragma unroll
                for (int e = 0; e < 4; e++) accS[tm][j][e] = 0.f;

#pragma unroll
        for (int k8 = 0; k8 < 4; k8++) {
            uint32_t bfr[8][2];
#pragma unroll
            for (int p = 0; p < 4; p++) {
                uint32_t r[4];
                ldsm4(sb + AT_K + SWZ((ch * 64 + p * 16 + b_sub) * 128 + k8 * 32 + b_cb), r);
                bfr[2 * p][0] = r[0]; bfr[2 * p][1] = r[1];
                bfr[2 * p + 1][0] = r[2]; bfr[2 * p + 1][1] = r[3];
            }
#pragma unroll
            for (int tm = 0; tm < 2; tm++)
#pragma unroll
                for (int j = 0; j < 8; j++)
                    mma8(accS[tm][j], qfr[tm][k8], bfr[j]);
        }

#pragma unroll
        for (int tm = 0; tm < 2; tm++)
#pragma unroll
            for (int hh = 0; hh < 2; hh++) {
                const int grow = wid * 32 + r4 + tm * 16 + hh * 8;
                const float* mp = mask + ((size_t)(n12 * N_SEQ + grow)) * N_SEQ + ch * 64 + c2;
#pragma unroll
                for (int j = 0; j < 8; j++) {
                    const float2 mm = *(const float2*)(mp + j * 8);
                    accS[tm][j][2 * hh + 0] += mm.x;
                    accS[tm][j][2 * hh + 1] += mm.y;
                }
            }

#pragma unroll
        for (int tm = 0; tm < 2; tm++)
#pragma unroll
            for (int hh = 0; hh < 2; hh++) {
                float mx = -1e30f;
#pragma unroll
                for (int j = 0; j < 8; j++) {
                    mx = fmaxf(mx, accS[tm][j][2 * hh + 0]);
                    mx = fmaxf(mx, accS[tm][j][2 * hh + 1]);
                }
                mx = fmaxf(mx, __shfl_xor_sync(0xffffffffu, mx, 1));
                mx = fmaxf(mx, __shfl_xor_sync(0xffffffffu, mx, 2));
                const float mnew = fmaxf(m_[tm][hh], mx);
                const float sc = __expf(m_[tm][hh] - mnew);
                m_[tm][hh] = mnew;
                l_[tm][hh] *= sc;
#pragma unroll
                for (int jn = 0; jn < 4; jn++) {
                    accpv[tm][jn][2 * hh + 0] *= sc;
                    accpv[tm][jn][2 * hh + 1] *= sc;
                }
                float rs = 0.f;
#pragma unroll
                for (int j = 0; j < 8; j++) {
                    const float p0 = __expf(accS[tm][j][2 * hh + 0] - mnew);
                    const float p1 = __expf(accS[tm][j][2 * hh + 1] - mnew);
                    rs += p0 + p1;
                    const int prow = r4 + tm * 16 + hh * 8;
                    uint32_t* pp = (uint32_t*)(smem + (pw - sb)) + prow * 68 + c2 + j * 8;
                    pp[0] = rna_tf32_u(p0);
                    pp[1] = rna_tf32_u(p1);
                }
                rs += __shfl_xor_sync(0xffffffffu, rs, 1);
                rs += __shfl_xor_sync(0xffffffffu, rs, 2);
                l_[tm][hh] += rs;
            }
        __syncwarp();

#pragma unroll
        for (int k8 = 0; k8 < 8; k8++) {
            uint32_t afrP[2][4];
#pragma unroll
            for (int tm = 0; tm < 2; tm++)
                ldsm4(pw + (tm * 16 + a_sub) * 272 + k8 * 32 + a_cb, afrP[tm]);
            uint32_t bfrV[4][2];
#pragma unroll
            for (int p = 0; p < 2; p++) {
                uint32_t r[4];
                ldsm4(sb + AT_VT + (p * 16 + b_sub) * 1040 + ch * 256 + k8 * 32 + b_cb, r);
                bfrV[2 * p][0] = r[0]; bfrV[2 * p][1] = r[1];
                bfrV[2 * p + 1][0] = r[2]; bfrV[2 * p + 1][1] = r[3];
            }
#pragma unroll
            for (int tm = 0; tm < 2; tm++)
#pragma unroll
                for (int jn = 0; jn < 4; jn++)
                    mma8(accpv[tm][jn], afrP[tm], bfrV[jn]);
        }
        __syncwarp();
    }

#pragma unroll
    for (int tm = 0; tm < 2; tm++)
#pragma unroll
        for (int hh = 0; hh < 2; hh++) {
            const float inv = 1.f / l_[tm][hh];
            const long row = base + wid * 32 + r4 + tm * 16 + hh * 8;
            float* op = out + row * E_DIM + hoff + c2;
#pragma unroll
            for (int jn = 0; jn < 4; jn++) {
                float2 o;
                o.x = rna_tf32(accpv[tm][jn][2 * hh + 0] * inv);
                o.y = rna_tf32(accpv[tm][jn][2 * hh + 1] * inv);
                *(float2*)(op + jn * 8) = o;
            }
        }
}

// ---------------------------------------------------------------------------
extern "C" void kernel_launch(void* const* d_in, const int* in_sizes, int n_in,
                              void* d_out, int out_size)
{
    const float* x     = (const float*)d_in[0];
    const float* mask  = (const float*)d_in[1];
    const float* Wq    = (const float*)d_in[2];
    const float* Wk    = (const float*)d_in[3];
    const float* Wv    = (const float*)d_in[4];
    const float* Wo    = (const float*)d_in[5];
    const float* bo    = (const float*)d_in[6];
    const float* W1    = (const float*)d_in[7];
    const float* bf1   = (const float*)d_in[8];
    const float* W2    = (const float*)d_in[9];
    const float* bf2   = (const float*)d_in[10];
    const float* g1    = (const float*)d_in[11];
    const float* beta1 = (const float*)d_in[12];
    const float* g2    = (const float*)d_in[13];
    const float* beta2 = (const float*)d_in[14];
    float* out = (float*)d_out;

    float *xr, *qkv, *attn, *h1, *h1r, *hid;
    float *WqkvT, *WoT, *W1T, *W2T;
    cudaGetSymbolAddress((void**)&xr,    g_xr);
    cudaGetSymbolAddress((void**)&qkv,   g_qkv);
    cudaGetSymbolAddress((void**)&attn,  g_attn);
    cudaGetSymbolAddress((void**)&h1,    g_h1);
    cudaGetSymbolAddress((void**)&h1r,   g_h1r);
    cudaGetSymbolAddress((void**)&hid,   g_hid);
    cudaGetSymbolAddress((void**)&WqkvT, g_WqkvT);
    cudaGetSymbolAddress((void**)&WoT,   g_WoT);
    cudaGetSymbolAddress((void**)&W1T,   g_W1T);
    cudaGetSymbolAddress((void**)&W2T,   g_W2T);

    auto k_qkv = gemm_mma<false, false, false, true,  false, false>;
    auto k_ff1 = gemm_mma<true,  true,  false, true,  false, false>;
    auto k_ln1 = gemm_mma<true,  false, true,  false, true,  true >;
    auto k_ln2 = gemm_mma<true,  false, true,  false, true,  false>;

    cudaFuncSetAttribute(k_qkv, cudaFuncAttributeMaxDynamicSharedMemorySize, GSMEM);
    cudaFuncSetAttribute(k_ff1, cudaFuncAttributeMaxDynamicSharedMemorySize, GSMEM);
    cudaFuncSetAttribute(k_ln1, cudaFuncAttributeMaxDynamicSharedMemorySize, GSMEM);
    cudaFuncSetAttribute(k_ln2, cudaFuncAttributeMaxDynamicSharedMemorySize, GSMEM);
    cudaFuncSetAttribute(attn_tc, cudaFuncAttributeMaxDynamicSharedMemorySize, AT_SMEM);

    // fused prep: x rounding + all weight transposes
    prep_kernel<<<NR_BLK + 768, 256>>>((const float4*)x, (float4*)xr,
                                       Wq, Wk, Wv, Wo, W1, W2,
                                       WqkvT, WoT, W1T, W2T);

    const dim3 blk(512);
    const dim3 gQKV(3, T_TOK / BM);   // Nt = 768
    const dim3 gE(1, T_TOK / BM);     // Nt = 256
    const dim3 gF(4, T_TOK / BM);     // Nt = 1024

    // fused QKV -> qkv[T,768] (rounded)
    k_qkv<<<gQKV, blk, GSMEM>>>(xr, WqkvT, qkv, nullptr, 3 * E_DIM, E_DIM,
                                nullptr, nullptr, nullptr, nullptr);

    // attention
    attn_tc<<<2048, 256, AT_SMEM>>>(qkv, mask, attn);

    // h1 = LN1(x + attn @ Wo + bo), h1r = round(h1)  [fused epilogue]
    k_ln1<<<gE, blk, GSMEM>>>(attn, WoT, h1, h1r, E_DIM, E_DIM,
                              bo, x, g1, beta1);

    // hid = round(relu(h1r @ W1 + bf1))
    k_ff1<<<gF, blk, GSMEM>>>(h1r, W1T, hid, nullptr, FF_DIM, E_DIM,
                              bf1, nullptr, nullptr, nullptr);

    // out = LN2(h1 + hid @ W2 + bf2)  [fused epilogue]
    k_ln2<<<gE, blk, GSMEM>>>(hid, W2T, out, nullptr, E_DIM, FF_DIM,
                              bf2, h1, g2, beta2);
}

// round 9
// speedup vs baseline: 4.3245x; 1.0622x over previous
#include <cuda_runtime.h>
#include <cstdint>

// ---------------------------------------------------------------------------
// EncoderLayer: B=16, N1=4, N2=4, N=256, E=256, H=8, DK=32
// T = 65536, E = 256, FF = 1024
// GEMMs: 256-thread CTAs, 2 CTAs/SM (warp tile 32x64), mma.sync tf32.
//   QKV/FF1: BM=128 BN=128 STG=3.  LN-fused (Wo/W2): BM=64 BN=256 STG=2.
// Flash attention on tensor cores. One fused prep kernel.
// ---------------------------------------------------------------------------

#define T_TOK  65536
#define E_DIM  256
#define FF_DIM 1024
#define N_SEQ  256
#define DK     32
#define SCALING 0.17677669529663687f
#define LN_EPS 1e-5f
#define BK 32

// ---------------- scratch ---------------------------------------------------
__device__ float g_xr   [T_TOK * E_DIM];
__device__ float g_qkv  [T_TOK * 3 * E_DIM];
__device__ float g_attn [T_TOK * E_DIM];
__device__ float g_h1   [T_TOK * E_DIM];
__device__ float g_h1r  [T_TOK * E_DIM];
__device__ float g_hid  [T_TOK * FF_DIM];
__device__ float g_WqkvT[3 * E_DIM * E_DIM];
__device__ float g_WoT  [E_DIM * E_DIM];
__device__ float g_W1T  [FF_DIM * E_DIM];
__device__ float g_W2T  [E_DIM * FF_DIM];

// ---------------- helpers ---------------------------------------------------
__device__ __forceinline__ uint32_t s2u(const void* p) {
    uint32_t a;
    asm("{ .reg .u64 t; cvta.to.shared.u64 t, %1; cvt.u32.u64 %0, t; }" : "=r"(a) : "l"(p));
    return a;
}
__device__ __forceinline__ float rna_tf32(float x) {
    uint32_t u;
    asm("cvt.rna.tf32.f32 %0, %1;" : "=r"(u) : "f"(x));
    return __uint_as_float(u);
}
__device__ __forceinline__ uint32_t rna_tf32_u(float x) {
    uint32_t u;
    asm("cvt.rna.tf32.f32 %0, %1;" : "=r"(u) : "f"(x));
    return u;
}
#define SWZ(o)  ((o) ^ (((o) >> 3) & 0x70))   // 128B rows

__device__ __forceinline__ void cpa16(uint32_t s, const void* g) {
    asm volatile("cp.async.cg.shared.global [%0], [%1], 16;" :: "r"(s), "l"(g));
}
#define CP_COMMIT() asm volatile("cp.async.commit_group;" ::: "memory")

__device__ __forceinline__ void ldsm4(uint32_t addr, uint32_t* r) {
    asm volatile("ldmatrix.sync.aligned.m8n8.x4.shared.b16 {%0,%1,%2,%3}, [%4];"
                 : "=r"(r[0]), "=r"(r[1]), "=r"(r[2]), "=r"(r[3]) : "r"(addr));
}
__device__ __forceinline__ void mma8(float* c, const uint32_t* a, const uint32_t* b) {
    asm volatile("mma.sync.aligned.m16n8k8.row.col.f32.tf32.tf32.f32 "
                 "{%0,%1,%2,%3}, {%4,%5,%6,%7}, {%8,%9}, {%0,%1,%2,%3};"
                 : "+f"(c[0]), "+f"(c[1]), "+f"(c[2]), "+f"(c[3])
                 : "r"(a[0]), "r"(a[1]), "r"(a[2]), "r"(a[3]), "r"(b[0]), "r"(b[1]));
}

// ---------------------------------------------------------------------------
// GEMM template: 256 threads, 8 warps (NWM x NWN), warp tile 32x64.
// Optional fused LayerNorm over 256-wide output rows (requires Nt == 256).
// ---------------------------------------------------------------------------
template<int BMt, int BNt, int STGt,
         bool BIAS, bool RELU, bool RES, bool ROUND, bool LN, bool DUAL>
__global__ __launch_bounds__(256, 2) void gemm_mma(
    const float* __restrict__ A, const float* __restrict__ BT,
    float* __restrict__ C, float* __restrict__ C2, int Nt, int Kt,
    const float* __restrict__ bias, const float* __restrict__ resid,
    const float* __restrict__ gamma, const float* __restrict__ beta)
{
    constexpr int NWM = BMt / 32;
    constexpr int NWN = BNt / 64;
    constexpr int ASZt = BMt * BK * 4;
    constexpr int BSZt = BNt * BK * 4;
    constexpr int STGBt = ASZt + BSZt;
    constexpr int REDBt = STGt * STGBt;

    extern __shared__ char smem[];
    const uint32_t sb = s2u(smem);
    const int tid = threadIdx.x;
    const int lane = tid & 31;
    const int wid = tid >> 5;
    const int wm = wid % NWM;
    const int wn = wid / NWM;

    const int m0 = blockIdx.y * BMt;
    const int n0 = blockIdx.x * BNt;
    const float* Ag = A + (size_t)m0 * Kt;
    const float* Bg = BT + (size_t)n0 * Kt;
    const int nC = Kt / BK;

    auto load_stage = [&](int s, int c) {
        const uint32_t ab = sb + s * STGBt;
        const uint32_t bb = ab + ASZt;
        const float* Ac = Ag + c * BK;
        const float* Bc = Bg + c * BK;
#pragma unroll
        for (int i = 0; i < BMt / 32; i++) {
            int g = i * 256 + tid, r = g >> 3, cc = g & 7;
            cpa16(ab + SWZ(r * 128 + cc * 16), Ac + (size_t)r * Kt + cc * 4);
        }
#pragma unroll
        for (int i = 0; i < BNt / 32; i++) {
            int g = i * 256 + tid, r = g >> 3, cc = g & 7;
            cpa16(bb + SWZ(r * 128 + cc * 16), Bc + (size_t)r * Kt + cc * 4);
        }
    };

#pragma unroll
    for (int j = 0; j < STGt - 1; j++) { load_stage(j, j); CP_COMMIT(); }

    float acc[2][8][4];
#pragma unroll
    for (int tm = 0; tm < 2; tm++)
#pragma unroll
        for (int j = 0; j < 8; j++)
#pragma unroll
            for (int e = 0; e < 4; e++) acc[tm][j][e] = 0.f;

    const int a_row = wm * 32 + (lane & 15);
    const int a_cb  = (lane >> 4) * 16;
    const int b_row = wn * 64 + (lane & 7) + ((lane >> 4) << 3);
    const int b_cb  = ((lane >> 3) & 1) * 16;

    for (int c = 0; c < nC; c++) {
        const int s = c % STGt;
        asm volatile("cp.async.wait_group %0;" :: "n"(STGt - 2) : "memory");
        __syncthreads();
        const int cn = c + STGt - 1;
        if (cn < nC) load_stage(cn % STGt, cn);
        CP_COMMIT();

        const uint32_t ab = sb + s * STGBt;
        const uint32_t bb = ab + ASZt;
#pragma unroll
        for (int k8 = 0; k8 < 4; k8++) {
            uint32_t afr[2][4], bfr[8][2];
#pragma unroll
            for (int tm = 0; tm < 2; tm++)
                ldsm4(ab + SWZ((a_row + tm * 16) * 128 + k8 * 32 + a_cb), afr[tm]);
#pragma unroll
            for (int p = 0; p < 4; p++) {
                uint32_t r[4];
                ldsm4(bb + SWZ((b_row + p * 16) * 128 + k8 * 32 + b_cb), r);
                bfr[2 * p][0] = r[0]; bfr[2 * p][1] = r[1];
                bfr[2 * p + 1][0] = r[2]; bfr[2 * p + 1][1] = r[3];
            }
#pragma unroll
            for (int tm = 0; tm < 2; tm++)
#pragma unroll
                for (int j = 0; j < 8; j++)
                    mma8(acc[tm][j], afr[tm], bfr[j]);
        }
        __syncthreads();
    }

    const int r4 = lane >> 2;
    const int c2 = (lane & 3) * 2;

    // ---- bias / residual / relu (in place) ----
#pragma unroll
    for (int tm = 0; tm < 2; tm++) {
#pragma unroll
        for (int j = 0; j < 8; j++) {
            const int gc = n0 + wn * 64 + j * 8 + c2;
#pragma unroll
            for (int h = 0; h < 2; h++) {
                float v0 = acc[tm][j][2 * h + 0];
                float v1 = acc[tm][j][2 * h + 1];
                if (BIAS) {
                    const float2 bb = *(const float2*)(bias + gc);
                    v0 += bb.x; v1 += bb.y;
                }
                if (RES) {
                    const int gr = m0 + wm * 32 + tm * 16 + h * 8 + r4;
                    const float2 rr = *(const float2*)(resid + (size_t)gr * Nt + gc);
                    v0 += rr.x; v1 += rr.y;
                }
                if (RELU) { v0 = fmaxf(v0, 0.f); v1 = fmaxf(v1, 0.f); }
                acc[tm][j][2 * h + 0] = v0;
                acc[tm][j][2 * h + 1] = v1;
            }
        }
    }

    if (LN) {
        // cross-warp LayerNorm over 256 cols (Nt == 256, n0 == 0)
        float2* red = (float2*)(smem + REDBt);
        __syncthreads();
#pragma unroll
        for (int tm = 0; tm < 2; tm++)
#pragma unroll
            for (int h = 0; h < 2; h++) {
                float s = 0.f, sq = 0.f;
#pragma unroll
                for (int j = 0; j < 8; j++) {
                    const float v0 = acc[tm][j][2 * h + 0];
                    const float v1 = acc[tm][j][2 * h + 1];
                    s += v0 + v1;
                    sq += v0 * v0 + v1 * v1;
                }
                s  += __shfl_xor_sync(0xffffffffu, s, 1);
                sq += __shfl_xor_sync(0xffffffffu, sq, 1);
                s  += __shfl_xor_sync(0xffffffffu, s, 2);
                sq += __shfl_xor_sync(0xffffffffu, sq, 2);
                if ((lane & 3) == 0) {
                    const int rl = wm * 32 + tm * 16 + h * 8 + r4;
                    red[rl * NWN + wn] = make_float2(s, sq);
                }
            }
        __syncthreads();

#pragma unroll
        for (int tm = 0; tm < 2; tm++)
#pragma unroll
            for (int h = 0; h < 2; h++) {
                const int rl = wm * 32 + tm * 16 + h * 8 + r4;
                float S = 0.f, SQ = 0.f;
#pragma unroll
                for (int i = 0; i < NWN; i++) {
                    const float2 p = red[rl * NWN + i];
                    S += p.x; SQ += p.y;
                }
                const float mean = S * (1.f / 256.f);
                const float var  = SQ * (1.f / 256.f) - mean * mean;
                const float rr   = rsqrtf(var + LN_EPS);
                const size_t crow = (size_t)(m0 + rl) * 256;
#pragma unroll
                for (int j = 0; j < 8; j++) {
                    const int gc = wn * 64 + j * 8 + c2;
                    const float2 gg = *(const float2*)(gamma + gc);
                    const float2 bb = *(const float2*)(beta + gc);
                    float o0 = (acc[tm][j][2 * h + 0] - mean) * rr * gg.x + bb.x;
                    float o1 = (acc[tm][j][2 * h + 1] - mean) * rr * gg.y + bb.y;
                    *(float2*)(C + crow + gc) = make_float2(o0, o1);
                    if (DUAL)
                        *(float2*)(C2 + crow + gc) =
                            make_float2(rna_tf32(o0), rna_tf32(o1));
                }
            }
    } else {
#pragma unroll
        for (int tm = 0; tm < 2; tm++) {
#pragma unroll
            for (int j = 0; j < 8; j++) {
                const int gc = n0 + wn * 64 + j * 8 + c2;
#pragma unroll
                for (int h = 0; h < 2; h++) {
                    const int gr = m0 + wm * 32 + tm * 16 + h * 8 + r4;
                    float v0 = acc[tm][j][2 * h + 0];
                    float v1 = acc[tm][j][2 * h + 1];
                    if (ROUND) { v0 = rna_tf32(v0); v1 = rna_tf32(v1); }
                    *(float2*)(C + (size_t)gr * Nt + gc) = make_float2(v0, v1);
                }
            }
        }
    }
}

// ---------------------------------------------------------------------------
// Fused prep: blocks [0, NR_BLK) round x -> xr; remaining transpose weights.
// ---------------------------------------------------------------------------
#define NR_BLK 8192

__global__ __launch_bounds__(256) void prep_kernel(
    const float4* __restrict__ x4, float4* __restrict__ xr4,
    const float* __restrict__ Wq, const float* __restrict__ Wk,
    const float* __restrict__ Wv, const float* __restrict__ Wo,
    const float* __restrict__ W1, const float* __restrict__ W2,
    float* __restrict__ WqkvT, float* __restrict__ WoT,
    float* __restrict__ W1T, float* __restrict__ W2T)
{
    const int b = blockIdx.x;
    const int tid = threadIdx.x;

    if (b < NR_BLK) {
        int i = b * 256 + tid;
#pragma unroll
        for (int it = 0; it < 2; it++) {
            float4 v = x4[i];
            v.x = rna_tf32(v.x); v.y = rna_tf32(v.y);
            v.z = rna_tf32(v.z); v.w = rna_tf32(v.w);
            xr4[i] = v;
            i += NR_BLK * 256;
        }
        return;
    }

    __shared__ float t[32][33];
    const int idx = b - NR_BLK;
    const float* W; float* WT; int K, N, kb, nb; float scale = 1.f;
    if (idx < 64) {
        W = Wq; WT = WqkvT; K = 256; N = 256; scale = SCALING;
        kb = (idx & 7) * 32; nb = (idx >> 3) * 32;
    } else if (idx < 128) {
        W = Wk; WT = WqkvT + 256 * 256; K = 256; N = 256;
        kb = ((idx - 64) & 7) * 32; nb = ((idx - 64) >> 3) * 32;
    } else if (idx < 192) {
        W = Wv; WT = WqkvT + 2 * 256 * 256; K = 256; N = 256;
        kb = ((idx - 128) & 7) * 32; nb = ((idx - 128) >> 3) * 32;
    } else if (idx < 256) {
        W = Wo; WT = WoT; K = 256; N = 256;
        kb = ((idx - 192) & 7) * 32; nb = ((idx - 192) >> 3) * 32;
    } else if (idx < 512) {
        W = W1; WT = W1T; K = 256; N = 1024;
        kb = ((idx - 256) & 7) * 32; nb = ((idx - 256) >> 3) * 32;
    } else {
        W = W2; WT = W2T; K = 1024; N = 256;
        kb = ((idx - 512) & 31) * 32; nb = ((idx - 512) >> 5) * 32;
    }
    const int tx = tid & 31, ty = tid >> 5;
    for (int i = ty; i < 32; i += 8)
        t[i][tx] = W[(size_t)(kb + i) * N + nb + tx];
    __syncthreads();
    for (int i = ty; i < 32; i += 8)
        WT[(size_t)(nb + i) * K + kb + tx] = rna_tf32(t[tx][i] * scale);
}

// ---------------------------------------------------------------------------
// Tensor-core flash attention (proven rounds 4-8).
// ---------------------------------------------------------------------------
#define QKV_LD (3 * E_DIM)
#define AT_Q   0
#define AT_K   32768
#define AT_VT  65536
#define AT_P   98816
#define AT_SMEM (AT_P + 8 * 8704)

__global__ __launch_bounds__(256, 1) void attn_tc(
    const float* __restrict__ qkv, const float* __restrict__ mask,
    float* __restrict__ out)
{
    extern __shared__ char smem[];
    const uint32_t sb = s2u(smem);
    float* smf = (float*)smem;

    const int bx = blockIdx.x;
    const int g  = bx >> 3;
    const int h  = bx & 7;
    const long base = (long)g * N_SEQ;
    const int hoff = h * DK;
    const int n12 = g & 15;
    const int tid = threadIdx.x;
    const int lane = tid & 31;
    const int wid = tid >> 5;

#pragma unroll
    for (int t = 0; t < 8; t++) {
        const int idx = t * 256 + tid;
        const int row = idx >> 3, cg = idx & 7;
        const long src = (base + row) * QKV_LD + hoff + cg * 4;
        cpa16(sb + AT_Q + SWZ(row * 128 + cg * 16), qkv + src);
        cpa16(sb + AT_K + SWZ(row * 128 + cg * 16), qkv + src + E_DIM);
        cpa16(sb + AT_P + SWZ(row * 128 + cg * 16), qkv + src + 2 * E_DIM);
    }
    CP_COMMIT();
    asm volatile("cp.async.wait_group 0;" ::: "memory");
    __syncthreads();

#pragma unroll
    for (int t = 0; t < 8; t++) {
        const int idx = t * 256 + tid;
        const int key = idx >> 3, dg = idx & 7;
        float4 vv = *(const float4*)(smem + AT_P + SWZ(key * 128 + dg * 16));
        float* vt = smf + AT_VT / 4;
        vt[(dg * 4 + 0) * 260 + key] = vv.x;
        vt[(dg * 4 + 1) * 260 + key] = vv.y;
        vt[(dg * 4 + 2) * 260 + key] = vv.z;
        vt[(dg * 4 + 3) * 260 + key] = vv.w;
    }
    __syncthreads();

    const int a_sub = lane & 15;
    const int a_cb  = (lane >> 4) * 16;
    uint32_t qfr[2][4][4];
#pragma unroll
    for (int tm = 0; tm < 2; tm++)
#pragma unroll
        for (int k8 = 0; k8 < 4; k8++)
            ldsm4(sb + AT_Q + SWZ((wid * 32 + tm * 16 + a_sub) * 128 + k8 * 32 + a_cb),
                  qfr[tm][k8]);

    const int b_sub = (lane & 7) + ((lane >> 4) << 3);
    const int b_cb  = ((lane >> 3) & 1) * 16;

    float m_[2][2], l_[2][2], accpv[2][4][4];
#pragma unroll
    for (int tm = 0; tm < 2; tm++)
#pragma unroll
        for (int hh = 0; hh < 2; hh++) { m_[tm][hh] = -1e30f; l_[tm][hh] = 0.f; }
#pragma unroll
    for (int tm = 0; tm < 2; tm++)
#pragma unroll
        for (int jn = 0; jn < 4; jn++)
#pragma unroll
            for (int e = 0; e < 4; e++) accpv[tm][jn][e] = 0.f;

    const uint32_t pw = sb + AT_P + wid * 8704;
    const int r4 = lane >> 2;
    const int c2 = (lane & 3) * 2;

    for (int ch = 0; ch < 4; ch++) {
        float accS[2][8][4];
#pragma unroll
        for (int tm = 0; tm < 2; tm++)
#pragma unroll
            for (int j = 0; j < 8; j++)
#pragma unroll
                for (int e = 0; e < 4; e++) accS[tm][j][e] = 0.f;

#pragma unroll
        for (int k8 = 0; k8 < 4; k8++) {
            uint32_t bfr[8][2];
#pragma unroll
            for (int p = 0; p < 4; p++) {
                uint32_t r[4];
                ldsm4(sb + AT_K + SWZ((ch * 64 + p * 16 + b_sub) * 128 + k8 * 32 + b_cb), r);
                bfr[2 * p][0] = r[0]; bfr[2 * p][1] = r[1];
                bfr[2 * p + 1][0] = r[2]; bfr[2 * p + 1][1] = r[3];
            }
#pragma unroll
            for (int tm = 0; tm < 2; tm++)
#pragma unroll
                for (int j = 0; j < 8; j++)
                    mma8(accS[tm][j], qfr[tm][k8], bfr[j]);
        }

#pragma unroll
        for (int tm = 0; tm < 2; tm++)
#pragma unroll
            for (int hh = 0; hh < 2; hh++) {
                const int grow = wid * 32 + r4 + tm * 16 + hh * 8;
                const float* mp = mask + ((size_t)(n12 * N_SEQ + grow)) * N_SEQ + ch * 64 + c2;
#pragma unroll
                for (int j = 0; j < 8; j++) {
                    const float2 mm = *(const float2*)(mp + j * 8);
                    accS[tm][j][2 * hh + 0] += mm.x;
                    accS[tm][j][2 * hh + 1] += mm.y;
                }
            }

#pragma unroll
        for (int tm = 0; tm < 2; tm++)
#pragma unroll
            for (int hh = 0; hh < 2; hh++) {
                float mx = -1e30f;
#pragma unroll
                for (int j = 0; j < 8; j++) {
                    mx = fmaxf(mx, accS[tm][j][2 * hh + 0]);
                    mx = fmaxf(mx, accS[tm][j][2 * hh + 1]);
                }
                mx = fmaxf(mx, __shfl_xor_sync(0xffffffffu, mx, 1));
                mx = fmaxf(mx, __shfl_xor_sync(0xffffffffu, mx, 2));
                const float mnew = fmaxf(m_[tm][hh], mx);
                const float sc = __expf(m_[tm][hh] - mnew);
                m_[tm][hh] = mnew;
                l_[tm][hh] *= sc;
#pragma unroll
                for (int jn = 0; jn < 4; jn++) {
                    accpv[tm][jn][2 * hh + 0] *= sc;
                    accpv[tm][jn][2 * hh + 1] *= sc;
                }
                float rs = 0.f;
#pragma unroll
                for (int j = 0; j < 8; j++) {
                    const float p0 = __expf(accS[tm][j][2 * hh + 0] - mnew);
                    const float p1 = __expf(accS[tm][j][2 * hh + 1] - mnew);
                    rs += p0 + p1;
                    const int prow = r4 + tm * 16 + hh * 8;
                    uint32_t* pp = (uint32_t*)(smem + (pw - sb)) + prow * 68 + c2 + j * 8;
                    pp[0] = rna_tf32_u(p0);
                    pp[1] = rna_tf32_u(p1);
                }
                rs += __shfl_xor_sync(0xffffffffu, rs, 1);
                rs += __shfl_xor_sync(0xffffffffu, rs, 2);
                l_[tm][hh] += rs;
            }
        __syncwarp();

#pragma unroll
        for (int k8 = 0; k8 < 8; k8++) {
            uint32_t afrP[2][4];
#pragma unroll
            for (int tm = 0; tm < 2; tm++)
                ldsm4(pw + (tm * 16 + a_sub) * 272 + k8 * 32 + a_cb, afrP[tm]);
            uint32_t bfrV[4][2];
#pragma unroll
            for (int p = 0; p < 2; p++) {
                uint32_t r[4];
                ldsm4(sb + AT_VT + (p * 16 + b_sub) * 1040 + ch * 256 + k8 * 32 + b_cb, r);
                bfrV[2 * p][0] = r[0]; bfrV[2 * p][1] = r[1];
                bfrV[2 * p + 1][0] = r[2]; bfrV[2 * p + 1][1] = r[3];
            }
#pragma unroll
            for (int tm = 0; tm < 2; tm++)
#pragma unroll
                for (int jn = 0; jn < 4; jn++)
                    mma8(accpv[tm][jn], afrP[tm], bfrV[jn]);
        }
        __syncwarp();
    }

#pragma unroll
    for (int tm = 0; tm < 2; tm++)
#pragma unroll
        for (int hh = 0; hh < 2; hh++) {
            const float inv = 1.f / l_[tm][hh];
            const long row = base + wid * 32 + r4 + tm * 16 + hh * 8;
            float* op = out + row * E_DIM + hoff + c2;
#pragma unroll
            for (int jn = 0; jn < 4; jn++) {
                float2 o;
                o.x = rna_tf32(accpv[tm][jn][2 * hh + 0] * inv);
                o.y = rna_tf32(accpv[tm][jn][2 * hh + 1] * inv);
                *(float2*)(op + jn * 8) = o;
            }
        }
}

// ---------------------------------------------------------------------------
extern "C" void kernel_launch(void* const* d_in, const int* in_sizes, int n_in,
                              void* d_out, int out_size)
{
    const float* x     = (const float*)d_in[0];
    const float* mask  = (const float*)d_in[1];
    const float* Wq    = (const float*)d_in[2];
    const float* Wk    = (const float*)d_in[3];
    const float* Wv    = (const float*)d_in[4];
    const float* Wo    = (const float*)d_in[5];
    const float* bo    = (const float*)d_in[6];
    const float* W1    = (const float*)d_in[7];
    const float* bf1   = (const float*)d_in[8];
    const float* W2    = (const float*)d_in[9];
    const float* bf2   = (const float*)d_in[10];
    const float* g1    = (const float*)d_in[11];
    const float* beta1 = (const float*)d_in[12];
    const float* g2    = (const float*)d_in[13];
    const float* beta2 = (const float*)d_in[14];
    float* out = (float*)d_out;

    float *xr, *qkv, *attn, *h1, *h1r, *hid;
    float *WqkvT, *WoT, *W1T, *W2T;
    cudaGetSymbolAddress((void**)&xr,    g_xr);
    cudaGetSymbolAddress((void**)&qkv,   g_qkv);
    cudaGetSymbolAddress((void**)&attn,  g_attn);
    cudaGetSymbolAddress((void**)&h1,    g_h1);
    cudaGetSymbolAddress((void**)&h1r,   g_h1r);
    cudaGetSymbolAddress((void**)&hid,   g_hid);
    cudaGetSymbolAddress((void**)&WqkvT, g_WqkvT);
    cudaGetSymbolAddress((void**)&WoT,   g_WoT);
    cudaGetSymbolAddress((void**)&W1T,   g_W1T);
    cudaGetSymbolAddress((void**)&W2T,   g_W2T);

    // instantiations
    auto k_qkv = gemm_mma<128, 128, 3, false, false, false, true,  false, false>;
    auto k_ff1 = gemm_mma<128, 128, 3, true,  true,  false, true,  false, false>;
    auto k_ln1 = gemm_mma<64,  256, 2, true,  false, true,  false, true,  true >;
    auto k_ln2 = gemm_mma<64,  256, 2, true,  false, true,  false, true,  false>;

    const int smem_qf = 3 * (128 + 128) * 128;            // 98304
    const int smem_ln = 2 * (64 + 256) * 128 + 64 * 4 * 8; // 83968

    cudaFuncSetAttribute(k_qkv, cudaFuncAttributeMaxDynamicSharedMemorySize, smem_qf);
    cudaFuncSetAttribute(k_ff1, cudaFuncAttributeMaxDynamicSharedMemorySize, smem_qf);
    cudaFuncSetAttribute(k_ln1, cudaFuncAttributeMaxDynamicSharedMemorySize, smem_ln);
    cudaFuncSetAttribute(k_ln2, cudaFuncAttributeMaxDynamicSharedMemorySize, smem_ln);
    cudaFuncSetAttribute(attn_tc, cudaFuncAttributeMaxDynamicSharedMemorySize, AT_SMEM);

    // fused prep: x rounding + all weight transposes
    prep_kernel<<<NR_BLK + 768, 256>>>((const float4*)x, (float4*)xr,
                                       Wq, Wk, Wv, Wo, W1, W2,
                                       WqkvT, WoT, W1T, W2T);

    const dim3 blk(256);
    const dim3 gQKV(6, T_TOK / 128);   // Nt = 768, BN=128
    const dim3 gF(8, T_TOK / 128);     // Nt = 1024, BN=128
    const dim3 gLN(1, T_TOK / 64);     // Nt = 256, BM=64

    // fused QKV -> qkv[T,768] (rounded)
    k_qkv<<<gQKV, blk, smem_qf>>>(xr, WqkvT, qkv, nullptr, 3 * E_DIM, E_DIM,
                                  nullptr, nullptr, nullptr, nullptr);

    // attention
    attn_tc<<<2048, 256, AT_SMEM>>>(qkv, mask, attn);

    // h1 = LN1(x + attn @ Wo + bo), h1r = round(h1)  [fused epilogue]
    k_ln1<<<gLN, blk, smem_ln>>>(attn, WoT, h1, h1r, E_DIM, E_DIM,
                                 bo, x, g1, beta1);

    // hid = round(relu(h1r @ W1 + bf1))
    k_ff1<<<gF, blk, smem_qf>>>(h1r, W1T, hid, nullptr, FF_DIM, E_DIM,
                                bf1, nullptr, nullptr, nullptr);

    // out = LN2(h1 + hid @ W2 + bf2)  [fused epilogue]
    k_ln2<<<gLN, blk, smem_ln>>>(hid, W2T, out, nullptr, E_DIM, FF_DIM,
                                 bf2, h1, g2, beta2);
}

// round 10
// speedup vs baseline: 4.3719x; 1.0110x over previous
#include <cuda_runtime.h>
#include <cstdint>

// ---------------------------------------------------------------------------
// EncoderLayer: B=16, N1=4, N2=4, N=256, E=256, H=8, DK=32
// T = 65536, E = 256, FF = 1024
// GEMMs: 256-thread CTAs, 2 CTAs/SM, warp tile 32x64, mma.sync tf32.
//   QKV/FF1: BM=128 BN=128 STG=3 (RNDA: round A frags in-register).
//   LN-fused (Wo/W2): BM=64 BN=256 STG=2.
// Attention: flash, tensor cores, shuffle-based P conversion (no SMEM P),
//   2 CTAs/SM. Prep = weight transposes only.
// ---------------------------------------------------------------------------

#define T_TOK  65536
#define E_DIM  256
#define FF_DIM 1024
#define N_SEQ  256
#define DK     32
#define SCALING 0.17677669529663687f
#define LN_EPS 1e-5f
#define BK 32

// ---------------- scratch ---------------------------------------------------
__device__ float g_qkv  [T_TOK * 3 * E_DIM];
__device__ float g_attn [T_TOK * E_DIM];
__device__ float g_h1   [T_TOK * E_DIM];
__device__ float g_hid  [T_TOK * FF_DIM];
__device__ float g_WqkvT[3 * E_DIM * E_DIM];
__device__ float g_WoT  [E_DIM * E_DIM];
__device__ float g_W1T  [FF_DIM * E_DIM];
__device__ float g_W2T  [E_DIM * FF_DIM];

// ---------------- helpers ---------------------------------------------------
__device__ __forceinline__ uint32_t s2u(const void* p) {
    uint32_t a;
    asm("{ .reg .u64 t; cvta.to.shared.u64 t, %1; cvt.u32.u64 %0, t; }" : "=r"(a) : "l"(p));
    return a;
}
__device__ __forceinline__ float rna_tf32(float x) {
    uint32_t u;
    asm("cvt.rna.tf32.f32 %0, %1;" : "=r"(u) : "f"(x));
    return __uint_as_float(u);
}
__device__ __forceinline__ uint32_t rna_tf32_u(float x) {
    uint32_t u;
    asm("cvt.rna.tf32.f32 %0, %1;" : "=r"(u) : "f"(x));
    return u;
}
#define SWZ(o)  ((o) ^ (((o) >> 3) & 0x70))   // 128B rows

__device__ __forceinline__ void cpa16(uint32_t s, const void* g) {
    asm volatile("cp.async.cg.shared.global [%0], [%1], 16;" :: "r"(s), "l"(g));
}
#define CP_COMMIT() asm volatile("cp.async.commit_group;" ::: "memory")

__device__ __forceinline__ void ldsm4(uint32_t addr, uint32_t* r) {
    asm volatile("ldmatrix.sync.aligned.m8n8.x4.shared.b16 {%0,%1,%2,%3}, [%4];"
                 : "=r"(r[0]), "=r"(r[1]), "=r"(r[2]), "=r"(r[3]) : "r"(addr));
}
__device__ __forceinline__ void mma8(float* c, const uint32_t* a, const uint32_t* b) {
    asm volatile("mma.sync.aligned.m16n8k8.row.col.f32.tf32.tf32.f32 "
                 "{%0,%1,%2,%3}, {%4,%5,%6,%7}, {%8,%9}, {%0,%1,%2,%3};"
                 : "+f"(c[0]), "+f"(c[1]), "+f"(c[2]), "+f"(c[3])
                 : "r"(a[0]), "r"(a[1]), "r"(a[2]), "r"(a[3]), "r"(b[0]), "r"(b[1]));
}

// ---------------------------------------------------------------------------
// GEMM template: 256 threads, 8 warps (NWM x NWN), warp tile 32x64.
// RNDA: round A fragments to tf32 in-register (A unrounded fp32 in gmem).
// LN: fused LayerNorm over 256-wide output rows (requires Nt == 256).
// ---------------------------------------------------------------------------
template<int BMt, int BNt, int STGt,
         bool BIAS, bool RELU, bool RES, bool ROUND, bool LN, bool RNDA>
__global__ __launch_bounds__(256, 2) void gemm_mma(
    const float* __restrict__ A, const float* __restrict__ BT,
    float* __restrict__ C, int Nt, int Kt,
    const float* __restrict__ bias, const float* __restrict__ resid,
    const float* __restrict__ gamma, const float* __restrict__ beta)
{
    constexpr int NWM = BMt / 32;
    constexpr int NWN = BNt / 64;
    constexpr int ASZt = BMt * BK * 4;
    constexpr int BSZt = BNt * BK * 4;
    constexpr int STGBt = ASZt + BSZt;
    constexpr int REDBt = STGt * STGBt;

    extern __shared__ char smem[];
    const uint32_t sb = s2u(smem);
    const int tid = threadIdx.x;
    const int lane = tid & 31;
    const int wid = tid >> 5;
    const int wm = wid % NWM;
    const int wn = wid / NWM;

    const int m0 = blockIdx.y * BMt;
    const int n0 = blockIdx.x * BNt;
    const float* Ag = A + (size_t)m0 * Kt;
    const float* Bg = BT + (size_t)n0 * Kt;
    const int nC = Kt / BK;

    auto load_stage = [&](int s, int c) {
        const uint32_t ab = sb + s * STGBt;
        const uint32_t bb = ab + ASZt;
        const float* Ac = Ag + c * BK;
        const float* Bc = Bg + c * BK;
#pragma unroll
        for (int i = 0; i < BMt / 32; i++) {
            int g = i * 256 + tid, r = g >> 3, cc = g & 7;
            cpa16(ab + SWZ(r * 128 + cc * 16), Ac + (size_t)r * Kt + cc * 4);
        }
#pragma unroll
        for (int i = 0; i < BNt / 32; i++) {
            int g = i * 256 + tid, r = g >> 3, cc = g & 7;
            cpa16(bb + SWZ(r * 128 + cc * 16), Bc + (size_t)r * Kt + cc * 4);
        }
    };

#pragma unroll
    for (int j = 0; j < STGt - 1; j++) { load_stage(j, j); CP_COMMIT(); }

    float acc[2][8][4];
#pragma unroll
    for (int tm = 0; tm < 2; tm++)
#pragma unroll
        for (int j = 0; j < 8; j++)
#pragma unroll
            for (int e = 0; e < 4; e++) acc[tm][j][e] = 0.f;

    const int a_row = wm * 32 + (lane & 15);
    const int a_cb  = (lane >> 4) * 16;
    const int b_row = wn * 64 + (lane & 7) + ((lane >> 4) << 3);
    const int b_cb  = ((lane >> 3) & 1) * 16;

    for (int c = 0; c < nC; c++) {
        const int s = c % STGt;
        asm volatile("cp.async.wait_group %0;" :: "n"(STGt - 2) : "memory");
        __syncthreads();
        const int cn = c + STGt - 1;
        if (cn < nC) load_stage(cn % STGt, cn);
        CP_COMMIT();

        const uint32_t ab = sb + s * STGBt;
        const uint32_t bb = ab + ASZt;
#pragma unroll
        for (int k8 = 0; k8 < 4; k8++) {
            uint32_t afr[2][4], bfr[8][2];
#pragma unroll
            for (int tm = 0; tm < 2; tm++) {
                ldsm4(ab + SWZ((a_row + tm * 16) * 128 + k8 * 32 + a_cb), afr[tm]);
                if (RNDA) {
#pragma unroll
                    for (int e = 0; e < 4; e++)
                        afr[tm][e] = rna_tf32_u(__uint_as_float(afr[tm][e]));
                }
            }
#pragma unroll
            for (int p = 0; p < 4; p++) {
                uint32_t r[4];
                ldsm4(bb + SWZ((b_row + p * 16) * 128 + k8 * 32 + b_cb), r);
                bfr[2 * p][0] = r[0]; bfr[2 * p][1] = r[1];
                bfr[2 * p + 1][0] = r[2]; bfr[2 * p + 1][1] = r[3];
            }
#pragma unroll
            for (int tm = 0; tm < 2; tm++)
#pragma unroll
                for (int j = 0; j < 8; j++)
                    mma8(acc[tm][j], afr[tm], bfr[j]);
        }
        __syncthreads();
    }

    const int r4 = lane >> 2;
    const int c2 = (lane & 3) * 2;

    // ---- bias / residual / relu (in place) ----
#pragma unroll
    for (int tm = 0; tm < 2; tm++) {
#pragma unroll
        for (int j = 0; j < 8; j++) {
            const int gc = n0 + wn * 64 + j * 8 + c2;
#pragma unroll
            for (int h = 0; h < 2; h++) {
                float v0 = acc[tm][j][2 * h + 0];
                float v1 = acc[tm][j][2 * h + 1];
                if (BIAS) {
                    const float2 bb = *(const float2*)(bias + gc);
                    v0 += bb.x; v1 += bb.y;
                }
                if (RES) {
                    const int gr = m0 + wm * 32 + tm * 16 + h * 8 + r4;
                    const float2 rr = *(const float2*)(resid + (size_t)gr * Nt + gc);
                    v0 += rr.x; v1 += rr.y;
                }
                if (RELU) { v0 = fmaxf(v0, 0.f); v1 = fmaxf(v1, 0.f); }
                acc[tm][j][2 * h + 0] = v0;
                acc[tm][j][2 * h + 1] = v1;
            }
        }
    }

    if (LN) {
        // cross-warp LayerNorm over 256 cols (Nt == 256, n0 == 0)
        float2* red = (float2*)(smem + REDBt);
        __syncthreads();
#pragma unroll
        for (int tm = 0; tm < 2; tm++)
#pragma unroll
            for (int h = 0; h < 2; h++) {
                float s = 0.f, sq = 0.f;
#pragma unroll
                for (int j = 0; j < 8; j++) {
                    const float v0 = acc[tm][j][2 * h + 0];
                    const float v1 = acc[tm][j][2 * h + 1];
                    s += v0 + v1;
                    sq += v0 * v0 + v1 * v1;
                }
                s  += __shfl_xor_sync(0xffffffffu, s, 1);
                sq += __shfl_xor_sync(0xffffffffu, sq, 1);
                s  += __shfl_xor_sync(0xffffffffu, s, 2);
                sq += __shfl_xor_sync(0xffffffffu, sq, 2);
                if ((lane & 3) == 0) {
                    const int rl = wm * 32 + tm * 16 + h * 8 + r4;
                    red[rl * NWN + wn] = make_float2(s, sq);
                }
            }
        __syncthreads();

#pragma unroll
        for (int tm = 0; tm < 2; tm++)
#pragma unroll
            for (int h = 0; h < 2; h++) {
                const int rl = wm * 32 + tm * 16 + h * 8 + r4;
                float S = 0.f, SQ = 0.f;
#pragma unroll
                for (int i = 0; i < NWN; i++) {
                    const float2 p = red[rl * NWN + i];
                    S += p.x; SQ += p.y;
                }
                const float mean = S * (1.f / 256.f);
                const float var  = SQ * (1.f / 256.f) - mean * mean;
                const float rr   = rsqrtf(var + LN_EPS);
                const size_t crow = (size_t)(m0 + rl) * 256;
#pragma unroll
                for (int j = 0; j < 8; j++) {
                    const int gc = wn * 64 + j * 8 + c2;
                    const float2 gg = *(const float2*)(gamma + gc);
                    const float2 bb = *(const float2*)(beta + gc);
                    float o0 = (acc[tm][j][2 * h + 0] - mean) * rr * gg.x + bb.x;
                    float o1 = (acc[tm][j][2 * h + 1] - mean) * rr * gg.y + bb.y;
                    *(float2*)(C + crow + gc) = make_float2(o0, o1);
                }
            }
    } else {
#pragma unroll
        for (int tm = 0; tm < 2; tm++) {
#pragma unroll
            for (int j = 0; j < 8; j++) {
                const int gc = n0 + wn * 64 + j * 8 + c2;
#pragma unroll
                for (int h = 0; h < 2; h++) {
                    const int gr = m0 + wm * 32 + tm * 16 + h * 8 + r4;
                    float v0 = acc[tm][j][2 * h + 0];
                    float v1 = acc[tm][j][2 * h + 1];
                    if (ROUND) { v0 = rna_tf32(v0); v1 = rna_tf32(v1); }
                    *(float2*)(C + (size_t)gr * Nt + gc) = make_float2(v0, v1);
                }
            }
        }
    }
}

// ---------------------------------------------------------------------------
// Prep: transpose + round the 6 weight matrices (32x32 tiles) into [N,K].
// ---------------------------------------------------------------------------
__global__ __launch_bounds__(256) void prep_kernel(
    const float* __restrict__ Wq, const float* __restrict__ Wk,
    const float* __restrict__ Wv, const float* __restrict__ Wo,
    const float* __restrict__ W1, const float* __restrict__ W2,
    float* __restrict__ WqkvT, float* __restrict__ WoT,
    float* __restrict__ W1T, float* __restrict__ W2T)
{
    const int idx = blockIdx.x;
    const int tid = threadIdx.x;
    __shared__ float t[32][33];
    const float* W; float* WT; int K, N, kb, nb; float scale = 1.f;
    if (idx < 64) {
        W = Wq; WT = WqkvT; K = 256; N = 256; scale = SCALING;
        kb = (idx & 7) * 32; nb = (idx >> 3) * 32;
    } else if (idx < 128) {
        W = Wk; WT = WqkvT + 256 * 256; K = 256; N = 256;
        kb = ((idx - 64) & 7) * 32; nb = ((idx - 64) >> 3) * 32;
    } else if (idx < 192) {
        W = Wv; WT = WqkvT + 2 * 256 * 256; K = 256; N = 256;
        kb = ((idx - 128) & 7) * 32; nb = ((idx - 128) >> 3) * 32;
    } else if (idx < 256) {
        W = Wo; WT = WoT; K = 256; N = 256;
        kb = ((idx - 192) & 7) * 32; nb = ((idx - 192) >> 3) * 32;
    } else if (idx < 512) {
        W = W1; WT = W1T; K = 256; N = 1024;
        kb = ((idx - 256) & 7) * 32; nb = ((idx - 256) >> 3) * 32;
    } else {
        W = W2; WT = W2T; K = 1024; N = 256;
        kb = ((idx - 512) & 31) * 32; nb = ((idx - 512) >> 5) * 32;
    }
    const int tx = tid & 31, ty = tid >> 5;
    for (int i = ty; i < 32; i += 8)
        t[i][tx] = W[(size_t)(kb + i) * N + nb + tx];
    __syncthreads();
    for (int i = ty; i < 32; i += 8)
        WT[(size_t)(nb + i) * K + kb + tx] = rna_tf32(t[tx][i] * scale);
}

// ---------------------------------------------------------------------------
// Tensor-core flash attention. SMEM: Q 32K, K 32K, VT 32x260 floats.
// P kept in registers; C->A fragment conversion via intra-quad shuffles.
// 2 CTAs/SM.
// ---------------------------------------------------------------------------
#define QKV_LD (3 * E_DIM)
#define AT_Q   0
#define AT_K   32768
#define AT_VT  65536
#define AT_SMEM (AT_VT + 32 * 260 * 4)   // 98816

__global__ __launch_bounds__(256, 2) void attn_tc(
    const float* __restrict__ qkv, const float* __restrict__ mask,
    float* __restrict__ out)
{
    extern __shared__ char smem[];
    const uint32_t sb = s2u(smem);
    float* smf = (float*)smem;

    const int bx = blockIdx.x;
    const int g  = bx >> 3;
    const int h  = bx & 7;
    const long base = (long)g * N_SEQ;
    const int hoff = h * DK;
    const int n12 = g & 15;
    const int tid = threadIdx.x;
    const int lane = tid & 31;
    const int wid = tid >> 5;

    // Q, K via cp.async (swizzled); V via LDG -> transposed STS into VT
#pragma unroll
    for (int t = 0; t < 8; t++) {
        const int idx = t * 256 + tid;
        const int row = idx >> 3, cg = idx & 7;
        const long src = (base + row) * QKV_LD + hoff + cg * 4;
        cpa16(sb + AT_Q + SWZ(row * 128 + cg * 16), qkv + src);
        cpa16(sb + AT_K + SWZ(row * 128 + cg * 16), qkv + src + E_DIM);
    }
    CP_COMMIT();
    {
        float* vt = smf + AT_VT / 4;
#pragma unroll
        for (int t = 0; t < 8; t++) {
            const int idx = t * 256 + tid;
            const int key = idx >> 3, dg = idx & 7;
            const float4 vv = *(const float4*)(qkv + (base + key) * QKV_LD + hoff
                                               + 2 * E_DIM + dg * 4);
            vt[(dg * 4 + 0) * 260 + key] = vv.x;
            vt[(dg * 4 + 1) * 260 + key] = vv.y;
            vt[(dg * 4 + 2) * 260 + key] = vv.z;
            vt[(dg * 4 + 3) * 260 + key] = vv.w;
        }
    }
    asm volatile("cp.async.wait_group 0;" ::: "memory");
    __syncthreads();

    const int a_sub = lane & 15;
    const int a_cb  = (lane >> 4) * 16;
    const int b_sub = (lane & 7) + ((lane >> 4) << 3);
    const int b_cb  = ((lane >> 3) & 1) * 16;
    const int r4 = lane >> 2;
    const int c2 = (lane & 3) * 2;
    const int qd = lane & 3;
    const int sl0 = (lane & ~3) | (qd >> 1);
    const int sl1 = sl0 + 2;
    const bool odd = qd & 1;

    float m_[2][2], l_[2][2], accpv[2][4][4];
#pragma unroll
    for (int tm = 0; tm < 2; tm++)
#pragma unroll
        for (int hh = 0; hh < 2; hh++) { m_[tm][hh] = -1e30f; l_[tm][hh] = 0.f; }
#pragma unroll
    for (int tm = 0; tm < 2; tm++)
#pragma unroll
        for (int jn = 0; jn < 4; jn++)
#pragma unroll
            for (int e = 0; e < 4; e++) accpv[tm][jn][e] = 0.f;

    for (int ch = 0; ch < 4; ch++) {
        // ---- S = Q @ K^T for this 64-key chunk ----
        float accS[2][8][4];
#pragma unroll
        for (int tm = 0; tm < 2; tm++)
#pragma unroll
            for (int j = 0; j < 8; j++)
#pragma unroll
                for (int e = 0; e < 4; e++) accS[tm][j][e] = 0.f;

#pragma unroll
        for (int k8 = 0; k8 < 4; k8++) {
            uint32_t afr[2][4], bfr[8][2];
#pragma unroll
            for (int tm = 0; tm < 2; tm++)
                ldsm4(sb + AT_Q + SWZ((wid * 32 + tm * 16 + a_sub) * 128 + k8 * 32 + a_cb),
                      afr[tm]);
#pragma unroll
            for (int p = 0; p < 4; p++) {
                uint32_t r[4];
                ldsm4(sb + AT_K + SWZ((ch * 64 + p * 16 + b_sub) * 128 + k8 * 32 + b_cb), r);
                bfr[2 * p][0] = r[0]; bfr[2 * p][1] = r[1];
                bfr[2 * p + 1][0] = r[2]; bfr[2 * p + 1][1] = r[3];
            }
#pragma unroll
            for (int tm = 0; tm < 2; tm++)
#pragma unroll
                for (int j = 0; j < 8; j++)
                    mma8(accS[tm][j], afr[tm], bfr[j]);
        }

        // ---- add mask ----
#pragma unroll
        for (int tm = 0; tm < 2; tm++)
#pragma unroll
            for (int hh = 0; hh < 2; hh++) {
                const int grow = wid * 32 + r4 + tm * 16 + hh * 8;
                const float* mp = mask + ((size_t)(n12 * N_SEQ + grow)) * N_SEQ + ch * 64 + c2;
#pragma unroll
                for (int j = 0; j < 8; j++) {
                    const float2 mm = *(const float2*)(mp + j * 8);
                    accS[tm][j][2 * hh + 0] += mm.x;
                    accS[tm][j][2 * hh + 1] += mm.y;
                }
            }

        // ---- online softmax; overwrite accS with rna(p) ----
#pragma unroll
        for (int tm = 0; tm < 2; tm++)
#pragma unroll
            for (int hh = 0; hh < 2; hh++) {
                float mx = -1e30f;
#pragma unroll
                for (int j = 0; j < 8; j++) {
                    mx = fmaxf(mx, accS[tm][j][2 * hh + 0]);
                    mx = fmaxf(mx, accS[tm][j][2 * hh + 1]);
                }
                mx = fmaxf(mx, __shfl_xor_sync(0xffffffffu, mx, 1));
                mx = fmaxf(mx, __shfl_xor_sync(0xffffffffu, mx, 2));
                const float mnew = fmaxf(m_[tm][hh], mx);
                const float sc = __expf(m_[tm][hh] - mnew);
                m_[tm][hh] = mnew;
                l_[tm][hh] *= sc;
#pragma unroll
                for (int jn = 0; jn < 4; jn++) {
                    accpv[tm][jn][2 * hh + 0] *= sc;
                    accpv[tm][jn][2 * hh + 1] *= sc;
                }
                float rs = 0.f;
#pragma unroll
                for (int j = 0; j < 8; j++) {
                    const float p0 = __expf(accS[tm][j][2 * hh + 0] - mnew);
                    const float p1 = __expf(accS[tm][j][2 * hh + 1] - mnew);
                    rs += p0 + p1;
                    accS[tm][j][2 * hh + 0] = rna_tf32(p0);
                    accS[tm][j][2 * hh + 1] = rna_tf32(p1);
                }
                rs += __shfl_xor_sync(0xffffffffu, rs, 1);
                rs += __shfl_xor_sync(0xffffffffu, rs, 2);
                l_[tm][hh] += rs;
            }

        // ---- PV: C-frag -> A-frag via intra-quad shuffles, then mma ----
#pragma unroll
        for (int k8 = 0; k8 < 8; k8++) {
            uint32_t afrP[2][4];
#pragma unroll
            for (int tm = 0; tm < 2; tm++) {
                const float c0 = accS[tm][k8][0], c1 = accS[tm][k8][1];
                const float c2v = accS[tm][k8][2], c3v = accS[tm][k8][3];
                const float e0 = __shfl_sync(0xffffffffu, c0,  sl0);
                const float e1 = __shfl_sync(0xffffffffu, c1,  sl0);
                const float e2 = __shfl_sync(0xffffffffu, c2v, sl0);
                const float e3 = __shfl_sync(0xffffffffu, c3v, sl0);
                const float f0 = __shfl_sync(0xffffffffu, c0,  sl1);
                const float f1 = __shfl_sync(0xffffffffu, c1,  sl1);
                const float f2 = __shfl_sync(0xffffffffu, c2v, sl1);
                const float f3 = __shfl_sync(0xffffffffu, c3v, sl1);
                afrP[tm][0] = __float_as_uint(odd ? e1 : e0);  // (r4,   qd)
                afrP[tm][1] = __float_as_uint(odd ? e3 : e2);  // (r4+8, qd)
                afrP[tm][2] = __float_as_uint(odd ? f1 : f0);  // (r4,   qd+4)
                afrP[tm][3] = __float_as_uint(odd ? f3 : f2);  // (r4+8, qd+4)
            }
            uint32_t bfrV[4][2];
#pragma unroll
            for (int p = 0; p < 2; p++) {
                uint32_t r[4];
                ldsm4(sb + AT_VT + (p * 16 + b_sub) * 1040 + ch * 256 + k8 * 32 + b_cb, r);
                bfrV[2 * p][0] = r[0]; bfrV[2 * p][1] = r[1];
                bfrV[2 * p + 1][0] = r[2]; bfrV[2 * p + 1][1] = r[3];
            }
#pragma unroll
            for (int tm = 0; tm < 2; tm++)
#pragma unroll
                for (int jn = 0; jn < 4; jn++)
                    mma8(accpv[tm][jn], afrP[tm], bfrV[jn]);
        }
    }

    // ---- epilogue: out = rna(accpv / l) ----
#pragma unroll
    for (int tm = 0; tm < 2; tm++)
#pragma unroll
        for (int hh = 0; hh < 2; hh++) {
            const float inv = 1.f / l_[tm][hh];
            const long row = base + wid * 32 + r4 + tm * 16 + hh * 8;
            float* op = out + row * E_DIM + hoff + c2;
#pragma unroll
            for (int jn = 0; jn < 4; jn++) {
                float2 o;
                o.x = rna_tf32(accpv[tm][jn][2 * hh + 0] * inv);
                o.y = rna_tf32(accpv[tm][jn][2 * hh + 1] * inv);
                *(float2*)(op + jn * 8) = o;
            }
        }
}

// ---------------------------------------------------------------------------
extern "C" void kernel_launch(void* const* d_in, const int* in_sizes, int n_in,
                              void* d_out, int out_size)
{
    const float* x     = (const float*)d_in[0];
    const float* mask  = (const float*)d_in[1];
    const float* Wq    = (const float*)d_in[2];
    const float* Wk    = (const float*)d_in[3];
    const float* Wv    = (const float*)d_in[4];
    const float* Wo    = (const float*)d_in[5];
    const float* bo    = (const float*)d_in[6];
    const float* W1    = (const float*)d_in[7];
    const float* bf1   = (const float*)d_in[8];
    const float* W2    = (const float*)d_in[9];
    const float* bf2   = (const float*)d_in[10];
    const float* g1    = (const float*)d_in[11];
    const float* beta1 = (const float*)d_in[12];
    const float* g2    = (const float*)d_in[13];
    const float* beta2 = (const float*)d_in[14];
    float* out = (float*)d_out;

    float *qkv, *attn, *h1, *hid;
    float *WqkvT, *WoT, *W1T, *W2T;
    cudaGetSymbolAddress((void**)&qkv,   g_qkv);
    cudaGetSymbolAddress((void**)&attn,  g_attn);
    cudaGetSymbolAddress((void**)&h1,    g_h1);
    cudaGetSymbolAddress((void**)&hid,   g_hid);
    cudaGetSymbolAddress((void**)&WqkvT, g_WqkvT);
    cudaGetSymbolAddress((void**)&WoT,   g_WoT);
    cudaGetSymbolAddress((void**)&W1T,   g_W1T);
    cudaGetSymbolAddress((void**)&W2T,   g_W2T);

    // instantiations: <BM,BN,STG, BIAS,RELU,RES,ROUND,LN,RNDA>
    auto k_qkv = gemm_mma<128, 128, 3, false, false, false, true,  false, true >;
    auto k_ff1 = gemm_mma<128, 128, 3, true,  true,  false, true,  false, true >;
    auto k_ln  = gemm_mma<64,  256, 2, true,  false, true,  false, true,  false>;

    const int smem_qf = 3 * (128 + 128) * BK * 4;              // 98304
    const int smem_ln = 2 * (64 + 256) * BK * 4 + 64 * 4 * 8;  // 83968

    cudaFuncSetAttribute(k_qkv, cudaFuncAttributeMaxDynamicSharedMemorySize, smem_qf);
    cudaFuncSetAttribute(k_ff1, cudaFuncAttributeMaxDynamicSharedMemorySize, smem_qf);
    cudaFuncSetAttribute(k_ln,  cudaFuncAttributeMaxDynamicSharedMemorySize, smem_ln);
    cudaFuncSetAttribute(attn_tc, cudaFuncAttributeMaxDynamicSharedMemorySize, AT_SMEM);

    // prep: weight transposes only
    prep_kernel<<<768, 256>>>(Wq, Wk, Wv, Wo, W1, W2, WqkvT, WoT, W1T, W2T);

    const dim3 blk(256);
    const dim3 gQKV(6, T_TOK / 128);   // Nt = 768, BN=128
    const dim3 gF(8, T_TOK / 128);     // Nt = 1024, BN=128
    const dim3 gLN(1, T_TOK / 64);     // Nt = 256, BM=64

    // fused QKV -> qkv[T,768] (A rounded in-register, output rounded)
    k_qkv<<<gQKV, blk, smem_qf>>>(x, WqkvT, qkv, 3 * E_DIM, E_DIM,
                                  nullptr, nullptr, nullptr, nullptr);

    // attention
    attn_tc<<<2048, 256, AT_SMEM>>>(qkv, mask, attn);

    // h1 = LN1(x + attn @ Wo + bo)
    k_ln<<<gLN, blk, smem_ln>>>(attn, WoT, h1, E_DIM, E_DIM,
                                bo, x, g1, beta1);

    // hid = round(relu(h1 @ W1 + bf1))  (A=h1 rounded in-register)
    k_ff1<<<gF, blk, smem_qf>>>(h1, W1T, hid, FF_DIM, E_DIM,
                                bf1, nullptr, nullptr, nullptr);

    // out = LN2(h1 + hid @ W2 + bf2)
    k_ln<<<gLN, blk, smem_ln>>>(hid, W2T, out, E_DIM, FF_DIM,
                                bf2, h1, g2, beta2);
}